// round 1
// baseline (speedup 1.0000x reference)
#include <cuda_runtime.h>
#include <math.h>

#define NQ 32400
#define NT 32512          // 254 * 128 (padded query count)
#define CDIM 512
#define NCLS 19
#define KNN 9
#define HWIN (270*480)    // 129600
#define FULLHW (1080*1920)
#define CHUNK_ROWS 8100   // NQ/4 -> each dist chunk ~1.05GB

// ---------------- device scratch (static, allowed by harness rules) ----------
__device__ float g_feats[(size_t)NT * CDIM];   // ~66.6 MB, padded rows are zero-init
__device__ float g_fs[NT];                     // squared norms (pad zero)
__device__ int   g_cls[NQ];
__device__ float g_psq[NCLS];
// distance matrix split in 4 chunks of 8100 rows x 32400 cols (fp32)
__device__ float g_dist0[(size_t)CHUNK_ROWS * NQ];
__device__ float g_dist1[(size_t)CHUNK_ROWS * NQ];
__device__ float g_dist2[(size_t)CHUNK_ROWS * NQ];
__device__ float g_dist3[(size_t)CHUNK_ROWS * NQ];

__device__ __forceinline__ float* dist_row(int i) {
    int c = i / CHUNK_ROWS;
    int r = i - c * CHUNK_ROWS;
    float* base = (c == 0) ? g_dist0 : (c == 1) ? g_dist1 : (c == 2) ? g_dist2 : g_dist3;
    return base + (size_t)r * NQ;
}

// ---------------- packed f32x2 helpers ----------------
__device__ __forceinline__ unsigned long long pk2(float lo, float hi) {
    unsigned long long r;
    asm("mov.b64 %0, {%1,%2};" : "=l"(r) : "f"(lo), "f"(hi));
    return r;
}
__device__ __forceinline__ void fma2(unsigned long long& d, unsigned long long a, unsigned long long b) {
    asm("fma.rn.f32x2 %0, %1, %2, %0;" : "+l"(d) : "l"(a), "l"(b));
}
__device__ __forceinline__ float2 up2(unsigned long long v) {
    float2 f;
    asm("mov.b64 {%0,%1}, %2;" : "=f"(f.x), "=f"(f.y) : "l"(v));
    return f;
}

// ---------------- kernel 0: zero the output --------------------------------
__global__ void zero_kernel(float4* out, int n4) {
    int i = blockIdx.x * blockDim.x + threadIdx.x;
    if (i < n4) out[i] = make_float4(0.f, 0.f, 0.f, 0.f);
}

// ---------------- kernel 1: gather feats, |f|^2, argmax class --------------
__global__ void prep_kernel(const float* __restrict__ feat,
                            const float* __restrict__ outp,
                            const int* __restrict__ sidx) {
    const int i = blockIdx.x;
    const int tid = threadIdx.x;
    const int s = sidx[i];

    float acc = 0.f;
    float* dst = g_feats + (size_t)i * CDIM;
    for (int c = tid; c < CDIM; c += 128) {
        float v = __ldg(feat + (size_t)c * HWIN + s);
        dst[c] = v;
        acc += v * v;
    }
    __shared__ float red[128];
    __shared__ float sval[NCLS];
    red[tid] = acc;
    if (tid < NCLS) sval[tid] = __ldg(outp + (size_t)tid * HWIN + s);
    __syncthreads();
    for (int st = 64; st > 0; st >>= 1) {
        if (tid < st) red[tid] += red[tid + st];
        __syncthreads();
    }
    if (tid == 0) {
        g_fs[i] = red[0];
        float best = sval[0]; int bc = 0;
        #pragma unroll
        for (int c = 1; c < NCLS; c++) {
            if (sval[c] > best) { best = sval[c]; bc = c; }   // first-max wins (argmax)
        }
        g_cls[i] = bc;
    }
}

// ---------------- kernel 2: prototype squared norms -------------------------
__global__ void psq_kernel(const float* __restrict__ protos) {
    int w = threadIdx.x >> 5, lane = threadIdx.x & 31;
    for (int c = w; c < NCLS; c += 8) {
        float sacc = 0.f;
        for (int k = lane; k < CDIM; k += 32) {
            float v = protos[c * CDIM + k];
            sacc += v * v;
        }
        #pragma unroll
        for (int o = 16; o > 0; o >>= 1) sacc += __shfl_xor_sync(0xffffffffu, sacc, o);
        if (lane == 0) g_psq[c] = sacc;
    }
}

// ---------------- kernel 3: all-pairs squared distances (SGEMM-like) --------
// 128x128 tile per block, BK=16, 16x16 threads, 8x8 register tile, f32x2 FMA.
__global__ __launch_bounds__(256) void dist_kernel() {
    __shared__ float As[16][128];
    __shared__ float Bs[16][128];

    const int tid = threadIdx.x;
    const int tx = tid & 15, ty = tid >> 4;
    const int row0 = blockIdx.y * 128;   // queries
    const int col0 = blockIdx.x * 128;   // candidates

    unsigned long long acc[8][4];
    #pragma unroll
    for (int a = 0; a < 8; a++)
        #pragma unroll
        for (int b = 0; b < 4; b++) acc[a][b] = 0ull;

    const int v0 = tid * 2;

    for (int k0 = 0; k0 < CDIM; k0 += 16) {
        #pragma unroll
        for (int u = 0; u < 2; u++) {
            int v = v0 + u;
            int m = v >> 2;
            int kq = (v & 3) << 2;
            float4 ta = *(const float4*)(g_feats + (size_t)(row0 + m) * CDIM + k0 + kq);
            As[kq + 0][m] = ta.x; As[kq + 1][m] = ta.y;
            As[kq + 2][m] = ta.z; As[kq + 3][m] = ta.w;
            float4 tb = *(const float4*)(g_feats + (size_t)(col0 + m) * CDIM + k0 + kq);
            Bs[kq + 0][m] = tb.x; Bs[kq + 1][m] = tb.y;
            Bs[kq + 2][m] = tb.z; Bs[kq + 3][m] = tb.w;
        }
        __syncthreads();

        #pragma unroll
        for (int kk = 0; kk < 16; kk++) {
            const unsigned long long* bp = (const unsigned long long*)&Bs[kk][tx * 8];
            unsigned long long b0 = bp[0], b1 = bp[1], b2 = bp[2], b3 = bp[3];
            #pragma unroll
            for (int ii = 0; ii < 8; ii++) {
                float av = As[kk][ty * 8 + ii];
                unsigned long long a2 = pk2(av, av);
                fma2(acc[ii][0], a2, b0);
                fma2(acc[ii][1], a2, b1);
                fma2(acc[ii][2], a2, b2);
                fma2(acc[ii][3], a2, b3);
            }
        }
        __syncthreads();
    }

    // epilogue: d = |fi|^2 + |fj|^2 - 2*dot, clamp to 1e-12, store
    #pragma unroll
    for (int ii = 0; ii < 8; ii++) {
        int i = row0 + ty * 8 + ii;
        if (i >= NQ) continue;
        float fi = g_fs[i];
        float* orow = dist_row(i);
        #pragma unroll
        for (int jj = 0; jj < 4; jj++) {
            int j = col0 + tx * 8 + jj * 2;
            float2 dot = up2(acc[ii][jj]);
            float d0 = fmaxf(fi + g_fs[j]     - 2.f * dot.x, 1e-12f);
            float d1 = fmaxf(fi + g_fs[j + 1] - 2.f * dot.y, 1e-12f);
            if (j + 1 < NQ) {
                *(float2*)(orow + j) = make_float2(d0, d1);
            } else if (j < NQ) {
                orow[j] = d0;
            }
        }
    }
}

// ---------------- kernel 4: top-9 + entropy + prototype rank + scatter ------
__global__ __launch_bounds__(256) void topk_kernel(const float* __restrict__ protos,
                                                   const int* __restrict__ sidx,
                                                   float* __restrict__ out) {
    const int q = blockIdx.x;
    const int tid = threadIdx.x;

    __shared__ float sfeat[CDIM];
    __shared__ float sd[256 * KNN];
    __shared__ int   si[256 * KNN];
    __shared__ float sdp[NCLS];

    const float* frow = g_feats + (size_t)q * CDIM;
    for (int k = tid; k < CDIM; k += 256) sfeat[k] = frow[k];
    __syncthreads();

    // prototype distances (8 warps cover 19 classes)
    {
        int w = tid >> 5, lane = tid & 31;
        float fq = g_fs[q];
        for (int c = w; c < NCLS; c += 8) {
            float sacc = 0.f;
            for (int k = lane; k < CDIM; k += 32)
                sacc += sfeat[k] * __ldg(&protos[c * CDIM + k]);
            #pragma unroll
            for (int o = 16; o > 0; o >>= 1) sacc += __shfl_xor_sync(0xffffffffu, sacc, o);
            if (lane == 0) sdp[c] = fmaxf(fq + g_psq[c] - 2.f * sacc, 1e-12f);
        }
    }

    // per-thread register top-9 over strided row scan
    float ld[KNN]; int li[KNN];
    #pragma unroll
    for (int k = 0; k < KNN; k++) { ld[k] = 3.0e38f; li[k] = 0; }

    const float* drow = dist_row(q);
    for (int j = tid; j < NQ; j += 256) {
        float d = drow[j];
        if (d < ld[KNN - 1]) {
            ld[KNN - 1] = d; li[KNN - 1] = j;
            #pragma unroll
            for (int p = KNN - 1; p > 0; p--) {
                if (ld[p] < ld[p - 1]) {
                    float tf = ld[p]; ld[p] = ld[p - 1]; ld[p - 1] = tf;
                    int   ti = li[p]; li[p] = li[p - 1]; li[p - 1] = ti;
                }
            }
        }
    }

    #pragma unroll
    for (int k = 0; k < KNN; k++) { sd[tid * KNN + k] = ld[k]; si[tid * KNN + k] = li[k]; }
    __syncthreads();

    // tree merge of sorted 9-lists
    for (int s = 128; s > 0; s >>= 1) {
        if (tid < s) {
            float a[KNN], b[KNN], m[KNN];
            int ai[KNN], bi[KNN], mi[KNN];
            #pragma unroll
            for (int k = 0; k < KNN; k++) {
                a[k]  = sd[tid * KNN + k];       ai[k] = si[tid * KNN + k];
                b[k]  = sd[(tid + s) * KNN + k]; bi[k] = si[(tid + s) * KNN + k];
            }
            int ia = 0, ib = 0;
            #pragma unroll
            for (int o = 0; o < KNN; o++) {
                bool ta = (a[ia] < b[ib]) || (a[ia] == b[ib] && ai[ia] <= bi[ib]);
                if (ta) { m[o] = a[ia]; mi[o] = ai[ia]; ia++; }
                else    { m[o] = b[ib]; mi[o] = bi[ib]; ib++; }
            }
            #pragma unroll
            for (int k = 0; k < KNN; k++) { sd[tid * KNN + k] = m[k]; si[tid * KNN + k] = mi[k]; }
        }
        __syncthreads();
    }

    if (tid == 0) {
        // entropy of neighbor-class histogram
        int cnt[NCLS];
        #pragma unroll
        for (int c = 0; c < NCLS; c++) cnt[c] = 0;
        #pragma unroll
        for (int k = 0; k < KNN; k++) cnt[g_cls[si[k]]]++;

        float ent = 0.f;
        #pragma unroll
        for (int c = 0; c < NCLS; c++) {
            if (cnt[c] > 0) {
                float p = (float)cnt[c] * (1.f / 9.f);
                ent += -p * logf(p + 1e-6f);
            }
        }
        ent *= (1.f / logf(19.f));

        // rank of predicted class among prototype distances (stable ascending)
        int myc = g_cls[q];
        float dq = sdp[myc];
        int rank = 0;
        #pragma unroll
        for (int c = 0; c < NCLS; c++) {
            float v = sdp[c];
            if (v < dq || (v == dq && c < myc)) rank++;
        }
        float score = (float)rank * (1.f / 18.f);

        int s = sidx[q];
        out[s] = ent;                 // full_p (= ents)
        out[FULLHW + s] = score;      // full_e (= rank scores)
    }
}

// ---------------- launch ------------------------------------------------------
extern "C" void kernel_launch(void* const* d_in, const int* in_sizes, int n_in,
                              void* d_out, int out_size) {
    const float* feat   = nullptr;
    const float* outp   = nullptr;
    const float* protos = nullptr;
    const int*   sidx   = nullptr;
    for (int i = 0; i < n_in; i++) {
        switch (in_sizes[i]) {
            case 66355200: feat   = (const float*)d_in[i]; break;  // [1,512,270,480]
            case 2462400:  outp   = (const float*)d_in[i]; break;  // [1,19,270,480]
            case 9728:     protos = (const float*)d_in[i]; break;  // [1,19,512]
            case 32400:    sidx   = (const int*)d_in[i];   break;  // [N]
        }
    }
    float* out = (float*)d_out;

    int n4 = out_size / 4;
    zero_kernel<<<(n4 + 255) / 256, 256>>>((float4*)out, n4);

    prep_kernel<<<NQ, 128>>>(feat, outp, sidx);
    psq_kernel<<<1, 256>>>(protos);

    dim3 grid(254, 254);
    dist_kernel<<<grid, 256>>>();

    topk_kernel<<<NQ, 256>>>(protos, sidx, out);
}

// round 4
// speedup vs baseline: 2.6197x; 2.6197x over previous
#include <cuda_runtime.h>
#include <cuda_bf16.h>
#include <math.h>
#include <cstdint>

#define NQ 32400
#define NT 32512          // 254*128 padded
#define CDIM 512
#define NCLS 19
#define KNN 9
#define SHORTL 16
#define HWIN (270*480)
#define FULLHW (1080*1920)
#define NCHUNK 8          // K chunks of 64 bf16 (128B rows)
#define NTILE 254         // candidate tiles of 128
#define TOTCH (NTILE*NCHUNK)
#define ROWBLKS 254

// ---------------- device scratch ----------------
__device__ float g_feats[(size_t)NT * CDIM];   // fp32 gathered feats
__device__ float g_fs[NT];                     // |f|^2 (pads -> 1e30)
__device__ int   g_cls[NQ];
__device__ float g_psq[NCLS];
// bf16 feats, chunk-major [NCHUNK][NT][64], PRE-SWIZZLED (SW128 within 8-row x 128B atoms)
__device__ __align__(1024) __nv_bfloat16 g_featsb[(size_t)NCHUNK * NT * 64];
__device__ int g_short[(size_t)NT * SHORTL];

// ---------------- helpers ----------------
__device__ __forceinline__ uint32_t smem_u32(const void* p) {
    uint32_t a;
    asm("{ .reg .u64 t; cvta.to.shared.u64 t, %1; cvt.u32.u64 %0, t; }" : "=r"(a) : "l"(p));
    return a;
}
__device__ __forceinline__ void cp16(uint32_t dst, const void* src) {
    asm volatile("cp.async.cg.shared.global [%0], [%1], 16;" :: "r"(dst), "l"(src) : "memory");
}
__device__ __forceinline__ void cp_commit() {
    asm volatile("cp.async.commit_group;" ::: "memory");
}
template<int N> __device__ __forceinline__ void cp_wait() {
    asm volatile("cp.async.wait_group %0;" :: "n"(N) : "memory");
}
__device__ __forceinline__ void ldsm4(uint32_t& r0, uint32_t& r1, uint32_t& r2, uint32_t& r3, uint32_t addr) {
    asm volatile("ldmatrix.sync.aligned.m8n8.x4.shared.b16 {%0,%1,%2,%3}, [%4];"
                 : "=r"(r0), "=r"(r1), "=r"(r2), "=r"(r3) : "r"(addr));
}
__device__ __forceinline__ void mma16816(float* c, uint32_t a0, uint32_t a1, uint32_t a2, uint32_t a3,
                                         uint32_t b0, uint32_t b1) {
    asm volatile("mma.sync.aligned.m16n8k16.row.col.f32.bf16.bf16.f32 "
                 "{%0,%1,%2,%3}, {%4,%5,%6,%7}, {%8,%9}, {%0,%1,%2,%3};"
                 : "+f"(c[0]), "+f"(c[1]), "+f"(c[2]), "+f"(c[3])
                 : "r"(a0), "r"(a1), "r"(a2), "r"(a3), "r"(b0), "r"(b1));
}
__device__ __forceinline__ uint32_t sw128(uint32_t x) { return x ^ ((x >> 3) & 0x70); }

__device__ __forceinline__ void ins16(float (&d)[SHORTL], int (&ix)[SHORTL], float v, int j) {
    if (v < d[SHORTL - 1]) {
        d[SHORTL - 1] = v; ix[SHORTL - 1] = j;
        #pragma unroll
        for (int p = SHORTL - 1; p > 0; p--) {
            if (d[p] < d[p - 1]) {
                float tf = d[p]; d[p] = d[p - 1]; d[p - 1] = tf;
                int   ti = ix[p]; ix[p] = ix[p - 1]; ix[p - 1] = ti;
            }
        }
    }
}

// ---------------- kernel 0: zero output ----------------
__global__ void zero_kernel(float4* out, int n4) {
    int i = blockIdx.x * blockDim.x + threadIdx.x;
    if (i < n4) out[i] = make_float4(0.f, 0.f, 0.f, 0.f);
}

// ---------------- kernel 1: gather feats, |f|^2, argmax class ----------------
__global__ void prep_kernel(const float* __restrict__ feat,
                            const float* __restrict__ outp,
                            const int* __restrict__ sidx) {
    const int i = blockIdx.x;
    const int tid = threadIdx.x;
    const int s = sidx[i];

    float acc = 0.f;
    float* dst = g_feats + (size_t)i * CDIM;
    for (int c = tid; c < CDIM; c += 128) {
        float v = __ldg(feat + (size_t)c * HWIN + s);
        dst[c] = v;
        acc += v * v;
    }
    __shared__ float red[128];
    __shared__ float sval[NCLS];
    red[tid] = acc;
    if (tid < NCLS) sval[tid] = __ldg(outp + (size_t)tid * HWIN + s);
    __syncthreads();
    for (int st = 64; st > 0; st >>= 1) {
        if (tid < st) red[tid] += red[tid + st];
        __syncthreads();
    }
    if (tid == 0) {
        g_fs[i] = red[0];
        float best = sval[0]; int bc = 0;
        #pragma unroll
        for (int c = 1; c < NCLS; c++)
            if (sval[c] > best) { best = sval[c]; bc = c; }
        g_cls[i] = bc;
    }
}

// ---------------- kernel 2: prototype norms + fs padding ----------------
__global__ void psq_pad_kernel(const float* __restrict__ protos) {
    int tid = threadIdx.x;
    int w = tid >> 5, lane = tid & 31;
    for (int c = w; c < NCLS; c += 8) {
        float sacc = 0.f;
        for (int k = lane; k < CDIM; k += 32) {
            float v = protos[c * CDIM + k];
            sacc += v * v;
        }
        #pragma unroll
        for (int o = 16; o > 0; o >>= 1) sacc += __shfl_xor_sync(0xffffffffu, sacc, o);
        if (lane == 0) g_psq[c] = sacc;
    }
    if (tid < NT - NQ) g_fs[NQ + tid] = 1e30f;
}

// ---------------- kernel 3: fp32 -> bf16, chunk-major, pre-swizzled (pads zeroed) ----
__global__ void convert_kernel() {
    int idx = blockIdx.x * blockDim.x + threadIdx.x;   // one 16B group of 8 bf16
    if (idx >= NT * 64) return;
    int r  = idx >> 6;
    int g8 = idx & 63;
    int k  = g8 * 8;
    int c  = k >> 6;
    int kin = k & 63;

    uint4 u = make_uint4(0u, 0u, 0u, 0u);
    if (r < NQ) {
        const float4* src = (const float4*)(g_feats + (size_t)r * CDIM + k);
        float4 v0 = src[0], v1 = src[1];
        __nv_bfloat162 p0 = __floats2bfloat162_rn(v0.x, v0.y);
        __nv_bfloat162 p1 = __floats2bfloat162_rn(v0.z, v0.w);
        __nv_bfloat162 p2 = __floats2bfloat162_rn(v1.x, v1.y);
        __nv_bfloat162 p3 = __floats2bfloat162_rn(v1.z, v1.w);
        u.x = *(uint32_t*)&p0; u.y = *(uint32_t*)&p1;
        u.z = *(uint32_t*)&p2; u.w = *(uint32_t*)&p3;
    }
    size_t base = ((size_t)c * NT + (size_t)(r & ~7)) * 128;
    uint32_t inner = (uint32_t)((r & 7) * 128 + kin * 2);
    *(uint4*)((char*)g_featsb + base + sw128(inner)) = u;
}

// ---------------- kernel 4: HMMA GEMM + fused top-16 ----------------
#define SM_FS 0
#define SM_A 1024
#define SM_B (1024 + 131072)
#define SM_TOTAL (SM_B + 4 * 16384)

__global__ __launch_bounds__(256, 1) void dist_select_kernel() {
    extern __shared__ char smem[];
    const uint32_t sb = smem_u32(smem);
    float* sfs = (float*)(smem + SM_FS);

    const int tid = threadIdx.x;
    const int w = tid >> 5, l = tid & 31;
    const int qg = l >> 2, t4 = l & 3;
    const int row0 = blockIdx.x * 128;

    // ---- load A: 8 chunks x 16KB ----
    #pragma unroll
    for (int c = 0; c < NCHUNK; c++) {
        size_t gb = ((size_t)c * NT + row0) * 128;
        for (int o = tid * 16; o < 16384; o += 256 * 16)
            cp16(sb + SM_A + c * 16384 + o, (const char*)g_featsb + gb + o);
    }
    cp_commit();   // group: A

    // ---- prologue: B chunks g=0,1,2 (tile 0) ----
    #pragma unroll
    for (int g0 = 0; g0 < 3; g0++) {
        size_t gb = ((size_t)g0 * NT) * 128;           // tile 0, chunk g0
        uint32_t dst = sb + SM_B + (uint32_t)g0 * 16384;
        for (int o = tid * 16; o < 16384; o += 256 * 16)
            cp16(dst + o, (const char*)g_featsb + gb + o);
        cp_commit();
    }

    // ---- per-lane ldmatrix addressing (swizzle applied to FULL offset) ----
    // A: lane groups 0-7/8-15/16-23/24-31 -> (rows0-7,k0-7),(rows8-15,k0-7),(rows0-7,k8-15),(rows8-15,k8-15)
    const int rowlA = l & 15;
    const int halfA = (l >> 4) & 1;
    const uint32_t maskA = (uint32_t)(rowlA & 7) << 4;
    const uint32_t aRowBase = (uint32_t)(16 * w + rowlA) * 128;
    // B: m0=(n0-7,k0-7) m1=(n0-7,k8-15) m2=(n8-15,k0-7) m3=(n8-15,k8-15)
    const int rowlB = (l & 7) + ((l >> 4) << 3);
    const int halfB = (l >> 3) & 1;
    const uint32_t maskB = (uint32_t)(rowlB & 7) << 4;
    const uint32_t bRowBase = (uint32_t)rowlB * 128;

    const float fiA = g_fs[row0 + 16 * w + qg];
    const float fiB = g_fs[row0 + 16 * w + qg + 8];

    float acc[16][4];
    #pragma unroll
    for (int n = 0; n < 16; n++)
        #pragma unroll
        for (int c = 0; c < 4; c++) acc[n][c] = 0.f;

    float dA[SHORTL], dB[SHORTL]; int iA[SHORTL], iB[SHORTL];
    #pragma unroll
    for (int k = 0; k < SHORTL; k++) { dA[k] = 3.0e38f; dB[k] = 3.0e38f; iA[k] = 0; iB[k] = 0; }

    for (int g = 0; g < TOTCH; g++) {
        const int kc = g & 7;
        const int tile = g >> 3;

        __syncthreads();   // all warps done with chunk g-1 -> ring slot (g+3)&3 reusable
        int gl = g + 3;
        if (gl < TOTCH) {
            int tl = gl >> 3, kl = gl & 7;
            size_t gb = ((size_t)kl * NT + (size_t)tl * 128) * 128;
            uint32_t dst = sb + SM_B + (uint32_t)(gl & 3) * 16384;
            for (int o = tid * 16; o < 16384; o += 256 * 16)
                cp16(dst + o, (const char*)g_featsb + gb + o);
        }
        cp_commit();
        cp_wait<3>();
        __syncthreads();   // chunk g visible to all

        if (kc == 0 && tid < 128) sfs[tid] = g_fs[tile * 128 + tid];

        const uint32_t abase = sb + SM_A + (uint32_t)kc * 16384;
        const uint32_t bbase = sb + SM_B + (uint32_t)(g & 3) * 16384;
        #pragma unroll
        for (int ks = 0; ks < 4; ks++) {
            uint32_t a0, a1, a2, a3;
            uint32_t acol = ((uint32_t)(ks * 32 + halfA * 16)) ^ maskA;
            ldsm4(a0, a1, a2, a3, abase + aRowBase + acol);
            uint32_t bcol = ((uint32_t)(ks * 32 + halfB * 16)) ^ maskB;
            #pragma unroll
            for (int p = 0; p < 8; p++) {
                uint32_t b0, b1, b2, b3;
                ldsm4(b0, b1, b2, b3, bbase + (uint32_t)p * 2048 + bRowBase + bcol);
                mma16816(acc[2 * p],     a0, a1, a2, a3, b0, b1);
                mma16816(acc[2 * p + 1], a0, a1, a2, a3, b2, b3);
            }
        }

        if (kc == 7) {
            const int jbase = tile * 128 + 2 * t4;
            #pragma unroll
            for (int nt = 0; nt < 16; nt++) {
                float fj0 = sfs[nt * 8 + 2 * t4];
                float fj1 = sfs[nt * 8 + 2 * t4 + 1];
                int j = jbase + nt * 8;
                float vA0 = fmaxf(fmaf(-2.f, acc[nt][0], fiA + fj0), 1e-12f);
                float vA1 = fmaxf(fmaf(-2.f, acc[nt][1], fiA + fj1), 1e-12f);
                float vB0 = fmaxf(fmaf(-2.f, acc[nt][2], fiB + fj0), 1e-12f);
                float vB1 = fmaxf(fmaf(-2.f, acc[nt][3], fiB + fj1), 1e-12f);
                ins16(dA, iA, vA0, j);
                ins16(dA, iA, vA1, j + 1);
                ins16(dB, iB, vB0, j);
                ins16(dB, iB, vB1, j + 1);
                acc[nt][0] = 0.f; acc[nt][1] = 0.f; acc[nt][2] = 0.f; acc[nt][3] = 0.f;
            }
        }
    }

    // ---- final 4-way per-row merge (reuse A region) ----
    __syncthreads();
    float* dm = (float*)(smem + SM_A);
    int*   im = (int*)(smem + SM_A + 128 * 64 * 4);
    {
        int rA = 16 * w + qg, rB = rA + 8;
        #pragma unroll
        for (int k = 0; k < SHORTL; k++) {
            dm[rA * 64 + t4 * 16 + k] = dA[k];  im[rA * 64 + t4 * 16 + k] = iA[k];
            dm[rB * 64 + t4 * 16 + k] = dB[k];  im[rB * 64 + t4 * 16 + k] = iB[k];
        }
    }
    __syncthreads();
    if (tid < 128) {
        int row = row0 + tid;
        if (row < NQ) {
            float bd[SHORTL]; int bi[SHORTL];
            #pragma unroll
            for (int k = 0; k < SHORTL; k++) { bd[k] = 3.0e38f; bi[k] = 0; }
            for (int e = 0; e < 64; e++)
                ins16(bd, bi, dm[tid * 64 + e], im[tid * 64 + e]);
            #pragma unroll
            for (int k = 0; k < SHORTL; k++) g_short[(size_t)row * SHORTL + k] = bi[k];
        }
    }
}

// ---------------- kernel 5: exact fp32 re-rank + entropy + proto rank + scatter ----
__global__ __launch_bounds__(256) void rerank_kernel(const float* __restrict__ protos,
                                                     const int* __restrict__ sidx,
                                                     float* __restrict__ out) {
    const int q = blockIdx.x * 8 + (threadIdx.x >> 5);
    if (q >= NQ) return;
    const int lane = threadIdx.x & 31;
    const unsigned FULL = 0xffffffffu;

    float qv[16];
    const float* fr = g_feats + (size_t)q * CDIM;
    #pragma unroll
    for (int i = 0; i < 16; i++) qv[i] = fr[i * 32 + lane];
    const float fq = g_fs[q];

    int myidx = (lane < SHORTL) ? g_short[(size_t)q * SHORTL + lane] : 0x7fffffff;
    float myd = 1e38f;

    #pragma unroll 1
    for (int c = 0; c < SHORTL; c++) {
        int cj = __shfl_sync(FULL, myidx, c);
        const float* cr = g_feats + (size_t)cj * CDIM;
        float acc = 0.f;
        #pragma unroll
        for (int i = 0; i < 16; i++) acc += qv[i] * __ldg(&cr[i * 32 + lane]);
        #pragma unroll
        for (int o = 16; o > 0; o >>= 1) acc += __shfl_xor_sync(FULL, acc, o);
        float d = fmaxf(fq + __ldg(&g_fs[cj]) - 2.f * acc, 1e-12f);
        if (lane == c) myd = d;
    }

    int rank = 0;
    #pragma unroll
    for (int o = 0; o < SHORTL; o++) {
        float od = __shfl_sync(FULL, myd, o);
        int   oi = __shfl_sync(FULL, myidx, o);
        if (o != lane && (od < myd || (od == myd && oi < myidx))) rank++;
    }
    int nbcls = (lane < SHORTL && rank < KNN) ? g_cls[myidx] : -1;

    float ent = 0.f;
    #pragma unroll
    for (int c = 0; c < NCLS; c++) {
        int cnt = __popc(__ballot_sync(FULL, nbcls == c));
        if (cnt > 0) {
            float p = (float)cnt * (1.f / 9.f);
            ent += -p * logf(p + 1e-6f);
        }
    }
    ent *= (1.f / logf(19.f));

    float pd = 1e38f;
    #pragma unroll 1
    for (int c = 0; c < NCLS; c++) {
        float acc = 0.f;
        #pragma unroll
        for (int i = 0; i < 16; i++) acc += qv[i] * __ldg(&protos[c * CDIM + i * 32 + lane]);
        #pragma unroll
        for (int o = 16; o > 0; o >>= 1) acc += __shfl_xor_sync(FULL, acc, o);
        if (lane == c) pd = fmaxf(fq + g_psq[c] - 2.f * acc, 1e-12f);
    }
    int myc = g_cls[q];
    float refd = __shfl_sync(FULL, pd, myc);
    unsigned m = __ballot_sync(FULL, (lane < NCLS) && (pd < refd || (pd == refd && lane < myc)));
    int prank = __popc(m);

    if (lane == 0) {
        int s = sidx[q];
        out[s] = ent;
        out[FULLHW + s] = (float)prank * (1.f / 18.f);
    }
}

// ---------------- launch ----------------
extern "C" void kernel_launch(void* const* d_in, const int* in_sizes, int n_in,
                              void* d_out, int out_size) {
    const float* feat   = nullptr;
    const float* outp   = nullptr;
    const float* protos = nullptr;
    const int*   sidx   = nullptr;
    for (int i = 0; i < n_in; i++) {
        switch (in_sizes[i]) {
            case 66355200: feat   = (const float*)d_in[i]; break;
            case 2462400:  outp   = (const float*)d_in[i]; break;
            case 9728:     protos = (const float*)d_in[i]; break;
            case 32400:    sidx   = (const int*)d_in[i];   break;
        }
    }
    float* out = (float*)d_out;

    static bool attr_done = false;
    if (!attr_done) {
        cudaFuncSetAttribute(dist_select_kernel,
                             cudaFuncAttributeMaxDynamicSharedMemorySize, SM_TOTAL);
        attr_done = true;
    }

    int n4 = out_size / 4;
    zero_kernel<<<(n4 + 255) / 256, 256>>>((float4*)out, n4);
    prep_kernel<<<NQ, 128>>>(feat, outp, sidx);
    psq_pad_kernel<<<1, 256>>>(protos);
    convert_kernel<<<(NT * 64 + 255) / 256, 256>>>();
    dist_select_kernel<<<ROWBLKS, 256, SM_TOTAL>>>();
    rerank_kernel<<<(NQ + 7) / 8, 256>>>(protos, sidx, out);
}

// round 5
// speedup vs baseline: 4.5561x; 1.7392x over previous
#include <cuda_runtime.h>
#include <cuda_bf16.h>
#include <math.h>
#include <cstdint>

#define NQ 32400
#define NT 32512          // 254*128 padded
#define CDIM 512
#define NCLS 19
#define KNN 9
#define SHORTL 16
#define LANEL 10
#define HWIN (270*480)
#define FULLHW (1080*1920)
#define NCHUNK 8          // K chunks of 64 bf16 (128B rows)
#define NTILE 254         // candidate tiles of 128
#define TOTCH (NTILE*NCHUNK)
#define ROWBLKS 254
#define NSTAGE 5

// ---------------- device scratch ----------------
__device__ float g_feats[(size_t)NT * CDIM];   // fp32 gathered feats
__device__ float g_fs[NT];                     // |f|^2 (pads -> 1e30)
__device__ int   g_cls[NQ];
__device__ float g_psq[NCLS];
// bf16 feats, chunk-major [NCHUNK][NT][64], PRE-SWIZZLED (SW128 within 8-row x 128B atoms)
__device__ __align__(1024) __nv_bfloat16 g_featsb[(size_t)NCHUNK * NT * 64];
__device__ int g_short[(size_t)NT * SHORTL];

// ---------------- helpers ----------------
__device__ __forceinline__ uint32_t smem_u32(const void* p) {
    uint32_t a;
    asm("{ .reg .u64 t; cvta.to.shared.u64 t, %1; cvt.u32.u64 %0, t; }" : "=r"(a) : "l"(p));
    return a;
}
__device__ __forceinline__ void cp16(uint32_t dst, const void* src) {
    asm volatile("cp.async.cg.shared.global [%0], [%1], 16;" :: "r"(dst), "l"(src) : "memory");
}
__device__ __forceinline__ void cp_commit() {
    asm volatile("cp.async.commit_group;" ::: "memory");
}
template<int N> __device__ __forceinline__ void cp_wait() {
    asm volatile("cp.async.wait_group %0;" :: "n"(N) : "memory");
}
__device__ __forceinline__ void ldsm4(uint32_t& r0, uint32_t& r1, uint32_t& r2, uint32_t& r3, uint32_t addr) {
    asm volatile("ldmatrix.sync.aligned.m8n8.x4.shared.b16 {%0,%1,%2,%3}, [%4];"
                 : "=r"(r0), "=r"(r1), "=r"(r2), "=r"(r3) : "r"(addr));
}
__device__ __forceinline__ void mma16816(float* c, uint32_t a0, uint32_t a1, uint32_t a2, uint32_t a3,
                                         uint32_t b0, uint32_t b1) {
    asm volatile("mma.sync.aligned.m16n8k16.row.col.f32.bf16.bf16.f32 "
                 "{%0,%1,%2,%3}, {%4,%5,%6,%7}, {%8,%9}, {%0,%1,%2,%3};"
                 : "+f"(c[0]), "+f"(c[1]), "+f"(c[2]), "+f"(c[3])
                 : "r"(a0), "r"(a1), "r"(a2), "r"(a3), "r"(b0), "r"(b1));
}
__device__ __forceinline__ uint32_t sw128(uint32_t x) { return x ^ ((x >> 3) & 0x70); }

template<int L>
__device__ __forceinline__ void insL(float (&d)[L], int (&ix)[L], float v, int j) {
    if (v < d[L - 1]) {
        d[L - 1] = v; ix[L - 1] = j;
        #pragma unroll
        for (int p = L - 1; p > 0; p--) {
            if (d[p] < d[p - 1]) {
                float tf = d[p]; d[p] = d[p - 1]; d[p - 1] = tf;
                int   ti = ix[p]; ix[p] = ix[p - 1]; ix[p - 1] = ti;
            }
        }
    }
}

// ---------------- kernel 0: zero output + prototype norms + fs pad ----------------
__global__ void zpsq_kernel(const float* __restrict__ protos, float4* out, int n4) {
    int i = blockIdx.x * blockDim.x + threadIdx.x;
    if (i < n4) out[i] = make_float4(0.f, 0.f, 0.f, 0.f);
    if (blockIdx.x == 0) {
        int tid = threadIdx.x;
        int w = tid >> 5, lane = tid & 31;
        for (int c = w; c < NCLS; c += 8) {
            float sacc = 0.f;
            for (int k = lane; k < CDIM; k += 32) {
                float v = protos[c * CDIM + k];
                sacc += v * v;
            }
            #pragma unroll
            for (int o = 16; o > 0; o >>= 1) sacc += __shfl_xor_sync(0xffffffffu, sacc, o);
            if (lane == 0) g_psq[c] = sacc;
        }
        if (tid < NT - NQ) g_fs[NQ + tid] = 1e30f;
    }
}

// ---------------- kernel 1: gather feats, |f|^2, argmax class ----------------
__global__ void prep_kernel(const float* __restrict__ feat,
                            const float* __restrict__ outp,
                            const int* __restrict__ sidx) {
    const int i = blockIdx.x;
    const int tid = threadIdx.x;
    const int s = sidx[i];

    float acc = 0.f;
    float* dst = g_feats + (size_t)i * CDIM;
    for (int c = tid; c < CDIM; c += 128) {
        float v = __ldg(feat + (size_t)c * HWIN + s);
        dst[c] = v;
        acc += v * v;
    }
    __shared__ float red[128];
    __shared__ float sval[NCLS];
    red[tid] = acc;
    if (tid < NCLS) sval[tid] = __ldg(outp + (size_t)tid * HWIN + s);
    __syncthreads();
    for (int st = 64; st > 0; st >>= 1) {
        if (tid < st) red[tid] += red[tid + st];
        __syncthreads();
    }
    if (tid == 0) {
        g_fs[i] = red[0];
        float best = sval[0]; int bc = 0;
        #pragma unroll
        for (int c = 1; c < NCLS; c++)
            if (sval[c] > best) { best = sval[c]; bc = c; }
        g_cls[i] = bc;
    }
}

// ---------------- kernel 2: fp32 -> bf16, chunk-major, pre-swizzled (pads zeroed) ----
__global__ void convert_kernel() {
    int idx = blockIdx.x * blockDim.x + threadIdx.x;   // one 16B group of 8 bf16
    if (idx >= NT * 64) return;
    int r  = idx >> 6;
    int g8 = idx & 63;
    int k  = g8 * 8;
    int c  = k >> 6;
    int kin = k & 63;

    uint4 u = make_uint4(0u, 0u, 0u, 0u);
    if (r < NQ) {
        const float4* src = (const float4*)(g_feats + (size_t)r * CDIM + k);
        float4 v0 = src[0], v1 = src[1];
        __nv_bfloat162 p0 = __floats2bfloat162_rn(v0.x, v0.y);
        __nv_bfloat162 p1 = __floats2bfloat162_rn(v0.z, v0.w);
        __nv_bfloat162 p2 = __floats2bfloat162_rn(v1.x, v1.y);
        __nv_bfloat162 p3 = __floats2bfloat162_rn(v1.z, v1.w);
        u.x = *(uint32_t*)&p0; u.y = *(uint32_t*)&p1;
        u.z = *(uint32_t*)&p2; u.w = *(uint32_t*)&p3;
    }
    size_t base = ((size_t)c * NT + (size_t)(r & ~7)) * 128;
    uint32_t inner = (uint32_t)((r & 7) * 128 + kin * 2);
    *(uint4*)((char*)g_featsb + base + sw128(inner)) = u;
}

// ---------------- kernel 3: HMMA GEMM + fused top-K (4x2 warp tiling) ----------------
#define SM_FS 0
#define SM_A 1024
#define SM_B (1024 + 131072)
#define SM_TOTAL (SM_B + NSTAGE * 16384)   // 214016

__global__ __launch_bounds__(256, 1) void dist_select_kernel() {
    extern __shared__ char smem[];
    const uint32_t sb = smem_u32(smem);
    float* sfs = (float*)(smem + SM_FS);

    const int tid = threadIdx.x;
    const int w = tid >> 5, l = tid & 31;
    const int qg = l >> 2, t4 = l & 3;
    const int wr = w >> 1, wc = w & 1;           // 4x2 warp grid
    const int row0 = blockIdx.x * 128;

    // ---- load A: 8 chunks x 16KB (group 0) ----
    #pragma unroll
    for (int c = 0; c < NCHUNK; c++) {
        size_t gb = ((size_t)c * NT + row0) * 128;
        for (int o = tid * 16; o < 16384; o += 256 * 16)
            cp16(sb + SM_A + c * 16384 + o, (const char*)g_featsb + gb + o);
    }
    cp_commit();

    // ---- prologue: B stages 0..3 (tile 0 chunks 0..3) ----
    #pragma unroll
    for (int g0 = 0; g0 < 4; g0++) {
        size_t gb = ((size_t)g0 * NT) * 128;
        uint32_t dst = sb + SM_B + (uint32_t)g0 * 16384;
        for (int o = tid * 16; o < 16384; o += 256 * 16)
            cp16(dst + o, (const char*)g_featsb + gb + o);
        cp_commit();
    }

    // ---- per-lane ldmatrix addressing ----
    const int rowlA = l & 15;
    const int halfA = (l >> 4) & 1;
    const uint32_t maskA = (uint32_t)(rowlA & 7) << 4;
    const uint32_t aRowBase = (uint32_t)(wr * 32 + rowlA) * 128;
    const int rowlB = (l & 7) + ((l >> 4) << 3);
    const int halfB = (l >> 3) & 1;
    const uint32_t maskB = (uint32_t)(rowlB & 7) << 4;
    const uint32_t bRowBase = (uint32_t)(wc * 64 + rowlB) * 128;

    float fi[4];
    #pragma unroll
    for (int r = 0; r < 4; r++) fi[r] = g_fs[row0 + wr * 32 + r * 8 + qg];

    float acc[2][8][4];
    #pragma unroll
    for (int m = 0; m < 2; m++)
        #pragma unroll
        for (int n = 0; n < 8; n++)
            #pragma unroll
            for (int c = 0; c < 4; c++) acc[m][n][c] = 0.f;

    float sld[4][LANEL]; int sli[4][LANEL];
    #pragma unroll
    for (int s = 0; s < 4; s++)
        #pragma unroll
        for (int k = 0; k < LANEL; k++) { sld[s][k] = 3.0e38f; sli[s][k] = 0; }

    int slot = 0, islot = 4;
    for (int g = 0; g < TOTCH; g++) {
        const int kc = g & 7;
        const int tile = g >> 3;

        cp_wait<3>();          // own copies of stage g complete
        __syncthreads();       // visible to all; all warps done with stage g-1

        int gl = g + 4;        // issue stage g+4 into slot of g-1
        if (gl < TOTCH) {
            int tl = gl >> 3, kl = gl & 7;
            size_t gb = ((size_t)kl * NT + (size_t)tl * 128) * 128;
            uint32_t dst = sb + SM_B + (uint32_t)islot * 16384;
            for (int o = tid * 16; o < 16384; o += 256 * 16)
                cp16(dst + o, (const char*)g_featsb + gb + o);
        }
        cp_commit();
        if (++islot == NSTAGE) islot = 0;

        if (kc == 0 && tid < 128) sfs[tid] = g_fs[tile * 128 + tid];

        const uint32_t abase = sb + SM_A + (uint32_t)kc * 16384 + aRowBase;
        const uint32_t bbase = sb + SM_B + (uint32_t)slot * 16384 + bRowBase;
        if (++slot == NSTAGE) slot = 0;

        #pragma unroll
        for (int ks = 0; ks < 4; ks++) {
            uint32_t acol = ((uint32_t)(ks * 32 + halfA * 16)) ^ maskA;
            uint32_t bcol = ((uint32_t)(ks * 32 + halfB * 16)) ^ maskB;
            uint32_t a00, a01, a02, a03, a10, a11, a12, a13;
            ldsm4(a00, a01, a02, a03, abase + acol);
            ldsm4(a10, a11, a12, a13, abase + 2048 + acol);
            #pragma unroll
            for (int p = 0; p < 4; p++) {
                uint32_t b0, b1, b2, b3;
                ldsm4(b0, b1, b2, b3, bbase + (uint32_t)p * 2048 + bcol);
                mma16816(acc[0][2 * p],     a00, a01, a02, a03, b0, b1);
                mma16816(acc[0][2 * p + 1], a00, a01, a02, a03, b2, b3);
                mma16816(acc[1][2 * p],     a10, a11, a12, a13, b0, b1);
                mma16816(acc[1][2 * p + 1], a10, a11, a12, a13, b2, b3);
            }
        }

        if (kc == 7) {
            #pragma unroll
            for (int m = 0; m < 2; m++)
                #pragma unroll
                for (int n8 = 0; n8 < 8; n8++) {
                    int c0 = wc * 64 + n8 * 8 + 2 * t4;
                    float fj0 = sfs[c0], fj1 = sfs[c0 + 1];
                    int j = tile * 128 + c0;
                    float v00 = fmaxf(fmaf(-2.f, acc[m][n8][0], fi[2 * m] + fj0), 1e-12f);
                    float v01 = fmaxf(fmaf(-2.f, acc[m][n8][1], fi[2 * m] + fj1), 1e-12f);
                    float v10 = fmaxf(fmaf(-2.f, acc[m][n8][2], fi[2 * m + 1] + fj0), 1e-12f);
                    float v11 = fmaxf(fmaf(-2.f, acc[m][n8][3], fi[2 * m + 1] + fj1), 1e-12f);
                    insL<LANEL>(sld[2 * m],     sli[2 * m],     v00, j);
                    insL<LANEL>(sld[2 * m],     sli[2 * m],     v01, j + 1);
                    insL<LANEL>(sld[2 * m + 1], sli[2 * m + 1], v10, j);
                    insL<LANEL>(sld[2 * m + 1], sli[2 * m + 1], v11, j + 1);
                    acc[m][n8][0] = 0.f; acc[m][n8][1] = 0.f;
                    acc[m][n8][2] = 0.f; acc[m][n8][3] = 0.f;
                }
        }
    }

    // ---- final merge: 8 lane-lists x 10 per row -> top-16 (reuse A region) ----
    __syncthreads();
    float* dm = (float*)(smem + SM_A);                      // 128*80*4 = 40960
    int*   im = (int*)(smem + SM_A + 128 * 80 * 4);         // +40960
    {
        const int listid = wc * 4 + t4;
        #pragma unroll
        for (int lst = 0; lst < 4; lst++) {
            int rloc = wr * 32 + lst * 8 + qg;              // lst = 2m+h -> m*16+h*8
            // careful: lst order 0..3 maps rows {qg, qg+8, qg+16, qg+24}
            #pragma unroll
            for (int k = 0; k < LANEL; k++) {
                dm[rloc * 80 + listid * LANEL + k] = sld[lst][k];
                im[rloc * 80 + listid * LANEL + k] = sli[lst][k];
            }
        }
    }
    __syncthreads();
    if (tid < 128) {
        int row = row0 + tid;
        if (row < NQ) {
            float bd[SHORTL]; int bi[SHORTL];
            #pragma unroll
            for (int k = 0; k < SHORTL; k++) { bd[k] = 3.0e38f; bi[k] = 0; }
            for (int e = 0; e < 80; e++)
                insL<SHORTL>(bd, bi, dm[tid * 80 + e], im[tid * 80 + e]);
            #pragma unroll
            for (int k = 0; k < SHORTL; k++) g_short[(size_t)row * SHORTL + k] = bi[k];
        }
    }
}

// ---------------- kernel 4: exact fp32 re-rank + entropy + proto rank + scatter ----
__global__ __launch_bounds__(256) void rerank_kernel(const float* __restrict__ protos,
                                                     const int* __restrict__ sidx,
                                                     float* __restrict__ out) {
    const int q = blockIdx.x * 8 + (threadIdx.x >> 5);
    if (q >= NQ) return;
    const int lane = threadIdx.x & 31;
    const unsigned FULL = 0xffffffffu;

    float qv[16];
    const float* fr = g_feats + (size_t)q * CDIM;
    #pragma unroll
    for (int i = 0; i < 16; i++) qv[i] = fr[i * 32 + lane];
    const float fq = g_fs[q];

    int myidx = (lane < SHORTL) ? g_short[(size_t)q * SHORTL + lane] : 0x7fffffff;
    float myd = 1e38f;

    #pragma unroll 1
    for (int c = 0; c < SHORTL; c++) {
        int cj = __shfl_sync(FULL, myidx, c);
        const float* cr = g_feats + (size_t)cj * CDIM;
        float acc = 0.f;
        #pragma unroll
        for (int i = 0; i < 16; i++) acc += qv[i] * __ldg(&cr[i * 32 + lane]);
        #pragma unroll
        for (int o = 16; o > 0; o >>= 1) acc += __shfl_xor_sync(FULL, acc, o);
        float d = fmaxf(fq + __ldg(&g_fs[cj]) - 2.f * acc, 1e-12f);
        if (lane == c) myd = d;
    }

    int rank = 0;
    #pragma unroll
    for (int o = 0; o < SHORTL; o++) {
        float od = __shfl_sync(FULL, myd, o);
        int   oi = __shfl_sync(FULL, myidx, o);
        if (o != lane && (od < myd || (od == myd && oi < myidx))) rank++;
    }
    int nbcls = (lane < SHORTL && rank < KNN) ? g_cls[myidx] : -1;

    float ent = 0.f;
    #pragma unroll
    for (int c = 0; c < NCLS; c++) {
        int cnt = __popc(__ballot_sync(FULL, nbcls == c));
        if (cnt > 0) {
            float p = (float)cnt * (1.f / 9.f);
            ent += -p * logf(p + 1e-6f);
        }
    }
    ent *= (1.f / logf(19.f));

    float pd = 1e38f;
    #pragma unroll 1
    for (int c = 0; c < NCLS; c++) {
        float acc = 0.f;
        #pragma unroll
        for (int i = 0; i < 16; i++) acc += qv[i] * __ldg(&protos[c * CDIM + i * 32 + lane]);
        #pragma unroll
        for (int o = 16; o > 0; o >>= 1) acc += __shfl_xor_sync(FULL, acc, o);
        if (lane == c) pd = fmaxf(fq + g_psq[c] - 2.f * acc, 1e-12f);
    }
    int myc = g_cls[q];
    float refd = __shfl_sync(FULL, pd, myc);
    unsigned m = __ballot_sync(FULL, (lane < NCLS) && (pd < refd || (pd == refd && lane < myc)));
    int prank = __popc(m);

    if (lane == 0) {
        int s = sidx[q];
        out[s] = ent;
        out[FULLHW + s] = (float)prank * (1.f / 18.f);
    }
}

// ---------------- launch ----------------
extern "C" void kernel_launch(void* const* d_in, const int* in_sizes, int n_in,
                              void* d_out, int out_size) {
    const float* feat   = nullptr;
    const float* outp   = nullptr;
    const float* protos = nullptr;
    const int*   sidx   = nullptr;
    for (int i = 0; i < n_in; i++) {
        switch (in_sizes[i]) {
            case 66355200: feat   = (const float*)d_in[i]; break;
            case 2462400:  outp   = (const float*)d_in[i]; break;
            case 9728:     protos = (const float*)d_in[i]; break;
            case 32400:    sidx   = (const int*)d_in[i];   break;
        }
    }
    float* out = (float*)d_out;

    static bool attr_done = false;
    if (!attr_done) {
        cudaFuncSetAttribute(dist_select_kernel,
                             cudaFuncAttributeMaxDynamicSharedMemorySize, SM_TOTAL);
        attr_done = true;
    }

    int n4 = out_size / 4;
    zpsq_kernel<<<(n4 + 255) / 256, 256>>>(protos, (float4*)out, n4);
    prep_kernel<<<NQ, 128>>>(feat, outp, sidx);
    convert_kernel<<<(NT * 64 + 255) / 256, 256>>>();
    dist_select_kernel<<<ROWBLKS, 256, SM_TOTAL>>>();
    rerank_kernel<<<(NQ + 7) / 8, 256>>>(protos, sidx, out);
}

// round 6
// speedup vs baseline: 4.8315x; 1.0604x over previous
#include <cuda_runtime.h>
#include <cuda_bf16.h>
#include <math.h>
#include <cstdint>

#define NQ 32400
#define NT 32512          // 254*128 padded
#define CDIM 512
#define NCLS 19
#define KNN 9
#define SHORTL 16
#define LANEL 10
#define HWIN (270*480)
#define FULLHW (1080*1920)
#define NCHUNK 8          // K chunks of 64 bf16 (128B rows)
#define NTILE 254         // candidate tiles of 128
#define TOTCH (NTILE*NCHUNK)
#define ROWBLKS 254
#define NSTAGE 5

// ---------------- device scratch ----------------
__device__ float g_feats[(size_t)NT * CDIM];   // fp32 gathered feats
__device__ float g_fs[NT];                     // |f|^2 (pads -> 1e30)
__device__ int   g_cls[NQ];
__device__ float g_psq[NCLS];
// bf16 feats, chunk-major [NCHUNK][NT][64], PRE-SWIZZLED (SW128 within 8-row x 128B atoms)
__device__ __align__(1024) __nv_bfloat16 g_featsb[(size_t)NCHUNK * NT * 64];
__device__ int g_short[(size_t)NT * SHORTL];

// ---------------- helpers ----------------
__device__ __forceinline__ uint32_t smem_u32(const void* p) {
    uint32_t a;
    asm("{ .reg .u64 t; cvta.to.shared.u64 t, %1; cvt.u32.u64 %0, t; }" : "=r"(a) : "l"(p));
    return a;
}
__device__ __forceinline__ void mbar_init(uint32_t a, uint32_t n) {
    asm volatile("mbarrier.init.shared.b64 [%0], %1;" :: "r"(a), "r"(n) : "memory");
}
__device__ __forceinline__ void mbar_expect(uint32_t a, uint32_t bytes) {
    asm volatile("mbarrier.arrive.expect_tx.shared.b64 _, [%0], %1;" :: "r"(a), "r"(bytes) : "memory");
}
__device__ __forceinline__ void mbar_wait_acq(uint32_t a, uint32_t ph) {
    asm volatile(
        "{\n\t.reg .pred P;\n"
        "W%=:\n\t"
        "mbarrier.try_wait.parity.acquire.cta.shared::cta.b64 P, [%0], %1, 0x989680;\n\t"
        "@P bra D%=;\n\t"
        "bra W%=;\n"
        "D%=:\n\t}"
        :: "r"(a), "r"(ph) : "memory");
}
__device__ __forceinline__ void bulk_g2s(uint32_t dst, const void* src, uint32_t bytes, uint32_t mbar) {
    asm volatile(
        "cp.async.bulk.shared::cluster.global.mbarrier::complete_tx::bytes [%0], [%1], %2, [%3];"
        :: "r"(dst), "l"(src), "r"(bytes), "r"(mbar) : "memory");
}
__device__ __forceinline__ void fence_async_shared() {
    asm volatile("fence.proxy.async.shared::cta;" ::: "memory");
}
__device__ __forceinline__ void ldsm4(uint32_t& r0, uint32_t& r1, uint32_t& r2, uint32_t& r3, uint32_t addr) {
    asm volatile("ldmatrix.sync.aligned.m8n8.x4.shared.b16 {%0,%1,%2,%3}, [%4];"
                 : "=r"(r0), "=r"(r1), "=r"(r2), "=r"(r3) : "r"(addr));
}
__device__ __forceinline__ void mma16816(float* c, uint32_t a0, uint32_t a1, uint32_t a2, uint32_t a3,
                                         uint32_t b0, uint32_t b1) {
    asm volatile("mma.sync.aligned.m16n8k16.row.col.f32.bf16.bf16.f32 "
                 "{%0,%1,%2,%3}, {%4,%5,%6,%7}, {%8,%9}, {%0,%1,%2,%3};"
                 : "+f"(c[0]), "+f"(c[1]), "+f"(c[2]), "+f"(c[3])
                 : "r"(a0), "r"(a1), "r"(a2), "r"(a3), "r"(b0), "r"(b1));
}
__device__ __forceinline__ uint32_t sw128(uint32_t x) { return x ^ ((x >> 3) & 0x70); }

template<int L>
__device__ __forceinline__ void insL(float (&d)[L], int (&ix)[L], float v, int j) {
    if (v < d[L - 1]) {
        d[L - 1] = v; ix[L - 1] = j;
        #pragma unroll
        for (int p = L - 1; p > 0; p--) {
            if (d[p] < d[p - 1]) {
                float tf = d[p]; d[p] = d[p - 1]; d[p - 1] = tf;
                int   ti = ix[p]; ix[p] = ix[p - 1]; ix[p - 1] = ti;
            }
        }
    }
}

// ---------------- kernel 0: zero output + prototype norms + fs pad ----------------
__global__ void zpsq_kernel(const float* __restrict__ protos, float4* out, int n4) {
    int i = blockIdx.x * blockDim.x + threadIdx.x;
    if (i < n4) out[i] = make_float4(0.f, 0.f, 0.f, 0.f);
    if (blockIdx.x == 0) {
        int tid = threadIdx.x;
        int w = tid >> 5, lane = tid & 31;
        for (int c = w; c < NCLS; c += 8) {
            float sacc = 0.f;
            for (int k = lane; k < CDIM; k += 32) {
                float v = protos[c * CDIM + k];
                sacc += v * v;
            }
            #pragma unroll
            for (int o = 16; o > 0; o >>= 1) sacc += __shfl_xor_sync(0xffffffffu, sacc, o);
            if (lane == 0) g_psq[c] = sacc;
        }
        if (tid < NT - NQ) g_fs[NQ + tid] = 1e30f;
    }
}

// ---------------- kernel 1: gather feats, |f|^2, argmax class ----------------
__global__ void prep_kernel(const float* __restrict__ feat,
                            const float* __restrict__ outp,
                            const int* __restrict__ sidx) {
    const int i = blockIdx.x;
    const int tid = threadIdx.x;
    const int s = sidx[i];

    float acc = 0.f;
    float* dst = g_feats + (size_t)i * CDIM;
    for (int c = tid; c < CDIM; c += 128) {
        float v = __ldg(feat + (size_t)c * HWIN + s);
        dst[c] = v;
        acc += v * v;
    }
    __shared__ float red[128];
    __shared__ float sval[NCLS];
    red[tid] = acc;
    if (tid < NCLS) sval[tid] = __ldg(outp + (size_t)tid * HWIN + s);
    __syncthreads();
    for (int st = 64; st > 0; st >>= 1) {
        if (tid < st) red[tid] += red[tid + st];
        __syncthreads();
    }
    if (tid == 0) {
        g_fs[i] = red[0];
        float best = sval[0]; int bc = 0;
        #pragma unroll
        for (int c = 1; c < NCLS; c++)
            if (sval[c] > best) { best = sval[c]; bc = c; }
        g_cls[i] = bc;
    }
}

// ---------------- kernel 2: fp32 -> bf16, chunk-major, pre-swizzled (pads zeroed) ----
__global__ void convert_kernel() {
    int idx = blockIdx.x * blockDim.x + threadIdx.x;   // one 16B group of 8 bf16
    if (idx >= NT * 64) return;
    int r  = idx >> 6;
    int g8 = idx & 63;
    int k  = g8 * 8;
    int c  = k >> 6;
    int kin = k & 63;

    uint4 u = make_uint4(0u, 0u, 0u, 0u);
    if (r < NQ) {
        const float4* src = (const float4*)(g_feats + (size_t)r * CDIM + k);
        float4 v0 = src[0], v1 = src[1];
        __nv_bfloat162 p0 = __floats2bfloat162_rn(v0.x, v0.y);
        __nv_bfloat162 p1 = __floats2bfloat162_rn(v0.z, v0.w);
        __nv_bfloat162 p2 = __floats2bfloat162_rn(v1.x, v1.y);
        __nv_bfloat162 p3 = __floats2bfloat162_rn(v1.z, v1.w);
        u.x = *(uint32_t*)&p0; u.y = *(uint32_t*)&p1;
        u.z = *(uint32_t*)&p2; u.w = *(uint32_t*)&p3;
    }
    size_t base = ((size_t)c * NT + (size_t)(r & ~7)) * 128;
    uint32_t inner = (uint32_t)((r & 7) * 128 + kin * 2);
    *(uint4*)((char*)g_featsb + base + sw128(inner)) = u;
}

// ---------------- kernel 3: HMMA GEMM + fused top-K (bulk-copy pipeline) ----------------
#define SM_FS 0
#define SM_A 1024
#define SM_B (1024 + 131072)
#define SM_TOTAL (SM_B + NSTAGE * 16384)   // 214016

__global__ __launch_bounds__(256, 1) void dist_select_kernel() {
    extern __shared__ char smem[];
    const uint32_t sb = smem_u32(smem);
    float* sfs = (float*)(smem + SM_FS);
    const uint32_t MB_A = sb + 512;
    const uint32_t MB_B = sb + 520;        // 5 x 8B

    const int tid = threadIdx.x;
    const int w = tid >> 5, l = tid & 31;
    const int qg = l >> 2, t4 = l & 3;
    const int wr = w >> 1, wc = w & 1;     // 4x2 warp grid
    const int row0 = blockIdx.x * 128;

    if (tid == 0) {
        mbar_init(MB_A, 1);
        #pragma unroll
        for (int s = 0; s < NSTAGE; s++) mbar_init(MB_B + 8 * s, 1);
        fence_async_shared();
    }
    __syncthreads();

    if (tid == 0) {
        // A: 8 chunks x 16KB, one barrier
        mbar_expect(MB_A, 131072);
        #pragma unroll
        for (int c = 0; c < NCHUNK; c++)
            bulk_g2s(sb + SM_A + c * 16384,
                     (const char*)g_featsb + ((size_t)c * NT + row0) * 128, 16384, MB_A);
        // B prologue: chunks 0..3 into slots 0..3
        #pragma unroll
        for (int g0 = 0; g0 < 4; g0++) {
            mbar_expect(MB_B + 8 * g0, 16384);
            bulk_g2s(sb + SM_B + (uint32_t)g0 * 16384,
                     (const char*)g_featsb + ((size_t)g0 * NT) * 128, 16384, MB_B + 8 * g0);
        }
    }

    // ---- per-lane ldmatrix addressing ----
    const int rowlA = l & 15;
    const int halfA = (l >> 4) & 1;
    const uint32_t maskA = (uint32_t)(rowlA & 7) << 4;
    const uint32_t aRowBase = (uint32_t)(wr * 32 + rowlA) * 128;
    const int rowlB = (l & 7) + ((l >> 4) << 3);
    const int halfB = (l >> 3) & 1;
    const uint32_t maskB = (uint32_t)(rowlB & 7) << 4;
    const uint32_t bRowBase = (uint32_t)(wc * 64 + rowlB) * 128;

    float fi[4];
    #pragma unroll
    for (int r = 0; r < 4; r++) fi[r] = g_fs[row0 + wr * 32 + r * 8 + qg];

    float acc[2][8][4];
    #pragma unroll
    for (int m = 0; m < 2; m++)
        #pragma unroll
        for (int n = 0; n < 8; n++)
            #pragma unroll
            for (int c = 0; c < 4; c++) acc[m][n][c] = 0.f;

    float sld[4][LANEL]; int sli[4][LANEL];
    #pragma unroll
    for (int s = 0; s < 4; s++)
        #pragma unroll
        for (int k = 0; k < LANEL; k++) { sld[s][k] = 3.0e38f; sli[s][k] = 0; }

    mbar_wait_acq(MB_A, 0);    // A resident

    for (int g = 0; g < TOTCH; g++) {
        const int kc = g & 7;
        const int tile = g >> 3;

        __syncthreads();   // all warps done with chunk g-1 -> slot (g-1)%5 == (g+4)%5 reusable
        if (tid == 0) {
            int gl = g + 4;
            if (gl < TOTCH) {
                int tl = gl >> 3, kl = gl & 7;
                int slot = gl % NSTAGE;
                mbar_expect(MB_B + 8 * slot, 16384);
                bulk_g2s(sb + SM_B + (uint32_t)slot * 16384,
                         (const char*)g_featsb + ((size_t)kl * NT + (size_t)tl * 128) * 128,
                         16384, MB_B + 8 * slot);
            }
        }
        if (kc == 0 && tid < 128) sfs[tid] = g_fs[tile * 128 + tid];

        mbar_wait_acq(MB_B + 8 * (g % NSTAGE), (uint32_t)((g / NSTAGE) & 1));

        const uint32_t abase = sb + SM_A + (uint32_t)kc * 16384 + aRowBase;
        const uint32_t bbase = sb + SM_B + (uint32_t)(g % NSTAGE) * 16384 + bRowBase;

        #pragma unroll
        for (int ks = 0; ks < 4; ks++) {
            uint32_t acol = ((uint32_t)(ks * 32 + halfA * 16)) ^ maskA;
            uint32_t bcol = ((uint32_t)(ks * 32 + halfB * 16)) ^ maskB;
            uint32_t a00, a01, a02, a03, a10, a11, a12, a13;
            ldsm4(a00, a01, a02, a03, abase + acol);
            ldsm4(a10, a11, a12, a13, abase + 2048 + acol);
            #pragma unroll
            for (int p = 0; p < 4; p++) {
                uint32_t b0, b1, b2, b3;
                ldsm4(b0, b1, b2, b3, bbase + (uint32_t)p * 2048 + bcol);
                mma16816(acc[0][2 * p],     a00, a01, a02, a03, b0, b1);
                mma16816(acc[0][2 * p + 1], a00, a01, a02, a03, b2, b3);
                mma16816(acc[1][2 * p],     a10, a11, a12, a13, b0, b1);
                mma16816(acc[1][2 * p + 1], a10, a11, a12, a13, b2, b3);
            }
        }

        if (kc == 7) {
            #pragma unroll
            for (int m = 0; m < 2; m++)
                #pragma unroll
                for (int n8 = 0; n8 < 8; n8++) {
                    int c0 = wc * 64 + n8 * 8 + 2 * t4;
                    float fj0 = sfs[c0], fj1 = sfs[c0 + 1];
                    int j = tile * 128 + c0;
                    float v00 = fmaxf(fmaf(-2.f, acc[m][n8][0], fi[2 * m] + fj0), 1e-12f);
                    float v01 = fmaxf(fmaf(-2.f, acc[m][n8][1], fi[2 * m] + fj1), 1e-12f);
                    float v10 = fmaxf(fmaf(-2.f, acc[m][n8][2], fi[2 * m + 1] + fj0), 1e-12f);
                    float v11 = fmaxf(fmaf(-2.f, acc[m][n8][3], fi[2 * m + 1] + fj1), 1e-12f);
                    insL<LANEL>(sld[2 * m],     sli[2 * m],     v00, j);
                    insL<LANEL>(sld[2 * m],     sli[2 * m],     v01, j + 1);
                    insL<LANEL>(sld[2 * m + 1], sli[2 * m + 1], v10, j);
                    insL<LANEL>(sld[2 * m + 1], sli[2 * m + 1], v11, j + 1);
                    acc[m][n8][0] = 0.f; acc[m][n8][1] = 0.f;
                    acc[m][n8][2] = 0.f; acc[m][n8][3] = 0.f;
                }
        }
    }

    // ---- final merge: 8 lane-lists x 10 per row -> top-16 (reuse A region) ----
    __syncthreads();
    float* dm = (float*)(smem + SM_A);                      // 128*80*4 = 40960
    int*   im = (int*)(smem + SM_A + 128 * 80 * 4);         // +40960
    {
        const int listid = wc * 4 + t4;
        #pragma unroll
        for (int lst = 0; lst < 4; lst++) {
            int rloc = wr * 32 + lst * 8 + qg;
            #pragma unroll
            for (int k = 0; k < LANEL; k++) {
                dm[rloc * 80 + listid * LANEL + k] = sld[lst][k];
                im[rloc * 80 + listid * LANEL + k] = sli[lst][k];
            }
        }
    }
    __syncthreads();
    if (tid < 128) {
        int row = row0 + tid;
        if (row < NQ) {
            float bd[SHORTL]; int bi[SHORTL];
            #pragma unroll
            for (int k = 0; k < SHORTL; k++) { bd[k] = 3.0e38f; bi[k] = 0; }
            for (int e = 0; e < 80; e++)
                insL<SHORTL>(bd, bi, dm[tid * 80 + e], im[tid * 80 + e]);
            #pragma unroll
            for (int k = 0; k < SHORTL; k++) g_short[(size_t)row * SHORTL + k] = bi[k];
        }
    }
}

// ---------------- kernel 4: exact fp32 re-rank + entropy + proto rank + scatter ----
__global__ __launch_bounds__(256) void rerank_kernel(const float* __restrict__ protos,
                                                     const int* __restrict__ sidx,
                                                     float* __restrict__ out) {
    const int q = blockIdx.x * 8 + (threadIdx.x >> 5);
    if (q >= NQ) return;
    const int lane = threadIdx.x & 31;
    const unsigned FULL = 0xffffffffu;

    float qv[16];
    const float* fr = g_feats + (size_t)q * CDIM;
    #pragma unroll
    for (int i = 0; i < 16; i++) qv[i] = fr[i * 32 + lane];
    const float fq = g_fs[q];

    int myidx = (lane < SHORTL) ? g_short[(size_t)q * SHORTL + lane] : 0x7fffffff;
    float myd = 1e38f;

    #pragma unroll 1
    for (int c = 0; c < SHORTL; c++) {
        int cj = __shfl_sync(FULL, myidx, c);
        const float* cr = g_feats + (size_t)cj * CDIM;
        float acc = 0.f;
        #pragma unroll
        for (int i = 0; i < 16; i++) acc += qv[i] * __ldg(&cr[i * 32 + lane]);
        #pragma unroll
        for (int o = 16; o > 0; o >>= 1) acc += __shfl_xor_sync(FULL, acc, o);
        float d = fmaxf(fq + __ldg(&g_fs[cj]) - 2.f * acc, 1e-12f);
        if (lane == c) myd = d;
    }

    int rank = 0;
    #pragma unroll
    for (int o = 0; o < SHORTL; o++) {
        float od = __shfl_sync(FULL, myd, o);
        int   oi = __shfl_sync(FULL, myidx, o);
        if (o != lane && (od < myd || (od == myd && oi < myidx))) rank++;
    }
    int nbcls = (lane < SHORTL && rank < KNN) ? g_cls[myidx] : -1;

    float ent = 0.f;
    #pragma unroll
    for (int c = 0; c < NCLS; c++) {
        int cnt = __popc(__ballot_sync(FULL, nbcls == c));
        if (cnt > 0) {
            float p = (float)cnt * (1.f / 9.f);
            ent += -p * logf(p + 1e-6f);
        }
    }
    ent *= (1.f / logf(19.f));

    float pd = 1e38f;
    #pragma unroll 1
    for (int c = 0; c < NCLS; c++) {
        float acc = 0.f;
        #pragma unroll
        for (int i = 0; i < 16; i++) acc += qv[i] * __ldg(&protos[c * CDIM + i * 32 + lane]);
        #pragma unroll
        for (int o = 16; o > 0; o >>= 1) acc += __shfl_xor_sync(FULL, acc, o);
        if (lane == c) pd = fmaxf(fq + g_psq[c] - 2.f * acc, 1e-12f);
    }
    int myc = g_cls[q];
    float refd = __shfl_sync(FULL, pd, myc);
    unsigned m = __ballot_sync(FULL, (lane < NCLS) && (pd < refd || (pd == refd && lane < myc)));
    int prank = __popc(m);

    if (lane == 0) {
        int s = sidx[q];
        out[s] = ent;
        out[FULLHW + s] = (float)prank * (1.f / 18.f);
    }
}

// ---------------- launch ----------------
extern "C" void kernel_launch(void* const* d_in, const int* in_sizes, int n_in,
                              void* d_out, int out_size) {
    const float* feat   = nullptr;
    const float* outp   = nullptr;
    const float* protos = nullptr;
    const int*   sidx   = nullptr;
    for (int i = 0; i < n_in; i++) {
        switch (in_sizes[i]) {
            case 66355200: feat   = (const float*)d_in[i]; break;
            case 2462400:  outp   = (const float*)d_in[i]; break;
            case 9728:     protos = (const float*)d_in[i]; break;
            case 32400:    sidx   = (const int*)d_in[i];   break;
        }
    }
    float* out = (float*)d_out;

    static bool attr_done = false;
    if (!attr_done) {
        cudaFuncSetAttribute(dist_select_kernel,
                             cudaFuncAttributeMaxDynamicSharedMemorySize, SM_TOTAL);
        attr_done = true;
    }

    int n4 = out_size / 4;
    zpsq_kernel<<<(n4 + 255) / 256, 256>>>(protos, (float4*)out, n4);
    prep_kernel<<<NQ, 128>>>(feat, outp, sidx);
    convert_kernel<<<(NT * 64 + 255) / 256, 256>>>();
    dist_select_kernel<<<ROWBLKS, 256, SM_TOTAL>>>();
    rerank_kernel<<<(NQ + 7) / 8, 256>>>(protos, sidx, out);
}

// round 7
// speedup vs baseline: 5.9103x; 1.2233x over previous
#include <cuda_runtime.h>
#include <cuda_bf16.h>
#include <math.h>
#include <cstdint>

#define NQ 32400
#define NT 32512          // 254*128 padded
#define CDIM 512
#define NCLS 19
#define KNN 9
#define SHORTL 16
#define LANEL 9
#define HWIN (270*480)
#define FULLHW (1080*1920)
#define NCHUNK 8          // K chunks of 64 bf16 (128B rows)
#define NTILE 254         // candidate tiles of 128
#define TOTST (NTILE*4)   // 2-chunk stages
#define ROWBLKS 254
#define NSTAGE 3          // 32KB stages

// ---------------- device scratch ----------------
__device__ float g_feats[(size_t)NT * CDIM];   // fp32 gathered feats
__device__ float g_fs[NT];                     // |f|^2 (pads -> 1e30)
__device__ int   g_cls[NQ];
__device__ float g_psq[NCLS];
// bf16 feats, TILE-major: [tile][chunk][128 rows x 128B], SW128 pre-swizzled per 8-row atom
__device__ __align__(1024) __nv_bfloat16 g_featsb[(size_t)NCHUNK * NT * 64];
__device__ int g_short[(size_t)NT * SHORTL];

// ---------------- helpers ----------------
__device__ __forceinline__ uint32_t smem_u32(const void* p) {
    uint32_t a;
    asm("{ .reg .u64 t; cvta.to.shared.u64 t, %1; cvt.u32.u64 %0, t; }" : "=r"(a) : "l"(p));
    return a;
}
__device__ __forceinline__ void mbar_init(uint32_t a, uint32_t n) {
    asm volatile("mbarrier.init.shared.b64 [%0], %1;" :: "r"(a), "r"(n) : "memory");
}
__device__ __forceinline__ void mbar_expect(uint32_t a, uint32_t bytes) {
    asm volatile("mbarrier.arrive.expect_tx.shared.b64 _, [%0], %1;" :: "r"(a), "r"(bytes) : "memory");
}
__device__ __forceinline__ void mbar_wait_acq(uint32_t a, uint32_t ph) {
    asm volatile(
        "{\n\t.reg .pred P;\n"
        "W%=:\n\t"
        "mbarrier.try_wait.parity.acquire.cta.shared::cta.b64 P, [%0], %1, 0x989680;\n\t"
        "@P bra D%=;\n\t"
        "bra W%=;\n"
        "D%=:\n\t}"
        :: "r"(a), "r"(ph) : "memory");
}
__device__ __forceinline__ void bulk_g2s(uint32_t dst, const void* src, uint32_t bytes, uint32_t mbar) {
    asm volatile(
        "cp.async.bulk.shared::cluster.global.mbarrier::complete_tx::bytes [%0], [%1], %2, [%3];"
        :: "r"(dst), "l"(src), "r"(bytes), "r"(mbar) : "memory");
}
__device__ __forceinline__ void fence_async_shared() {
    asm volatile("fence.proxy.async.shared::cta;" ::: "memory");
}
__device__ __forceinline__ void ldsm4(uint32_t& r0, uint32_t& r1, uint32_t& r2, uint32_t& r3, uint32_t addr) {
    asm volatile("ldmatrix.sync.aligned.m8n8.x4.shared.b16 {%0,%1,%2,%3}, [%4];"
                 : "=r"(r0), "=r"(r1), "=r"(r2), "=r"(r3) : "r"(addr));
}
__device__ __forceinline__ void mma16816(float* c, uint32_t a0, uint32_t a1, uint32_t a2, uint32_t a3,
                                         uint32_t b0, uint32_t b1) {
    asm volatile("mma.sync.aligned.m16n8k16.row.col.f32.bf16.bf16.f32 "
                 "{%0,%1,%2,%3}, {%4,%5,%6,%7}, {%8,%9}, {%0,%1,%2,%3};"
                 : "+f"(c[0]), "+f"(c[1]), "+f"(c[2]), "+f"(c[3])
                 : "r"(a0), "r"(a1), "r"(a2), "r"(a3), "r"(b0), "r"(b1));
}
__device__ __forceinline__ uint32_t sw128(uint32_t x) { return x ^ ((x >> 3) & 0x70); }

template<int L>
__device__ __forceinline__ void insL(float (&d)[L], int (&ix)[L], float v, int j) {
    if (v < d[L - 1]) {
        d[L - 1] = v; ix[L - 1] = j;
        #pragma unroll
        for (int p = L - 1; p > 0; p--) {
            if (d[p] < d[p - 1]) {
                float tf = d[p]; d[p] = d[p - 1]; d[p - 1] = tf;
                int   ti = ix[p]; ix[p] = ix[p - 1]; ix[p - 1] = ti;
            }
        }
    }
}

// ---------------- kernel 0: zero output + prototype norms + fs pad ----------------
__global__ void zpsq_kernel(const float* __restrict__ protos, float4* out, int n4) {
    int i = blockIdx.x * blockDim.x + threadIdx.x;
    if (i < n4) out[i] = make_float4(0.f, 0.f, 0.f, 0.f);
    if (blockIdx.x == 0) {
        int tid = threadIdx.x;
        int w = tid >> 5, lane = tid & 31;
        for (int c = w; c < NCLS; c += 8) {
            float sacc = 0.f;
            for (int k = lane; k < CDIM; k += 32) {
                float v = protos[c * CDIM + k];
                sacc += v * v;
            }
            #pragma unroll
            for (int o = 16; o > 0; o >>= 1) sacc += __shfl_xor_sync(0xffffffffu, sacc, o);
            if (lane == 0) g_psq[c] = sacc;
        }
        if (tid < NT - NQ) g_fs[NQ + tid] = 1e30f;
    }
}

// ---------------- kernel 1: gather feats, |f|^2, argmax class ----------------
__global__ void prep_kernel(const float* __restrict__ feat,
                            const float* __restrict__ outp,
                            const int* __restrict__ sidx) {
    const int i = blockIdx.x;
    const int tid = threadIdx.x;
    const int s = sidx[i];

    float acc = 0.f;
    float* dst = g_feats + (size_t)i * CDIM;
    for (int c = tid; c < CDIM; c += 128) {
        float v = __ldg(feat + (size_t)c * HWIN + s);
        dst[c] = v;
        acc += v * v;
    }
    __shared__ float red[128];
    __shared__ float sval[NCLS];
    red[tid] = acc;
    if (tid < NCLS) sval[tid] = __ldg(outp + (size_t)tid * HWIN + s);
    __syncthreads();
    for (int st = 64; st > 0; st >>= 1) {
        if (tid < st) red[tid] += red[tid + st];
        __syncthreads();
    }
    if (tid == 0) {
        g_fs[i] = red[0];
        float best = sval[0]; int bc = 0;
        #pragma unroll
        for (int c = 1; c < NCLS; c++)
            if (sval[c] > best) { best = sval[c]; bc = c; }
        g_cls[i] = bc;
    }
}

// ---------------- kernel 2: fp32 -> bf16, tile-major, pre-swizzled (pads zeroed) ----
__global__ void convert_kernel() {
    int idx = blockIdx.x * blockDim.x + threadIdx.x;   // one 16B group of 8 bf16
    if (idx >= NT * 64) return;
    int r  = idx >> 6;
    int g8 = idx & 63;
    int k  = g8 * 8;
    int c  = k >> 6;
    int kin = k & 63;

    uint4 u = make_uint4(0u, 0u, 0u, 0u);
    if (r < NQ) {
        const float4* src = (const float4*)(g_feats + (size_t)r * CDIM + k);
        float4 v0 = src[0], v1 = src[1];
        __nv_bfloat162 p0 = __floats2bfloat162_rn(v0.x, v0.y);
        __nv_bfloat162 p1 = __floats2bfloat162_rn(v0.z, v0.w);
        __nv_bfloat162 p2 = __floats2bfloat162_rn(v1.x, v1.y);
        __nv_bfloat162 p3 = __floats2bfloat162_rn(v1.z, v1.w);
        u.x = *(uint32_t*)&p0; u.y = *(uint32_t*)&p1;
        u.z = *(uint32_t*)&p2; u.w = *(uint32_t*)&p3;
    }
    // tile-major: [tile][chunk][16 atoms x 1024B]
    size_t base = ((size_t)(r >> 7) * NCHUNK + c) * 16384 + (size_t)((r >> 3) & 15) * 1024;
    uint32_t inner = (uint32_t)((r & 7) * 128 + kin * 2);
    *(uint4*)((char*)g_featsb + base + sw128(inner)) = u;
}

// ---------------- kernel 3: HMMA GEMM + fused top-K (512 thr, 8x2 warps) ----------------
#define SM_FS 0
#define SM_A 1024
#define SM_B (1024 + 131072)
#define SM_TOTAL (SM_B + NSTAGE * 32768)   // 230400

__global__ __launch_bounds__(512, 1) void dist_select_kernel() {
    extern __shared__ char smem[];
    const uint32_t sb = smem_u32(smem);
    float* sfs = (float*)(smem + SM_FS);
    const uint32_t MB_A = sb + 512;
    const uint32_t MB_B = sb + 520;        // 3 x 8B

    const int tid = threadIdx.x;
    const int w = tid >> 5, l = tid & 31;
    const int qg = l >> 2, t4 = l & 3;
    const int wr = w >> 1, wc = w & 1;     // 8x2 warp grid: 16 rows x 64 cols per warp
    const int row0 = blockIdx.x * 128;

    if (tid == 0) {
        mbar_init(MB_A, 1);
        #pragma unroll
        for (int s = 0; s < NSTAGE; s++) mbar_init(MB_B + 8 * s, 1);
        fence_async_shared();
    }
    __syncthreads();

    if (tid == 0) {
        // A: 128KB contiguous (tile-major), 8 bulk copies, one barrier
        mbar_expect(MB_A, 131072);
        const char* abase_g = (const char*)g_featsb + (size_t)(row0 >> 7) * NCHUNK * 16384;
        #pragma unroll
        for (int c = 0; c < NCHUNK; c++)
            bulk_g2s(sb + SM_A + c * 16384, abase_g + (size_t)c * 16384, 16384, MB_A);
        // B prologue: stages 0,1 (32KB each = 2 chunks)
        #pragma unroll
        for (int s0 = 0; s0 < 2; s0++) {
            mbar_expect(MB_B + 8 * s0, 32768);
            bulk_g2s(sb + SM_B + (uint32_t)s0 * 32768,
                     (const char*)g_featsb + (size_t)(s0 * 2) * 16384, 32768, MB_B + 8 * s0);
        }
    }

    // ---- per-lane ldmatrix addressing (same row/col fragment maps as passing R5/R6) ----
    const int rowlA = l & 15;
    const int halfA = (l >> 4) & 1;
    const uint32_t maskA = (uint32_t)(rowlA & 7) << 4;
    const uint32_t aRowBase = (uint32_t)(wr * 16 + rowlA) * 128;
    const int rowlB = (l & 7) + ((l >> 4) << 3);
    const int halfB = (l >> 3) & 1;
    const uint32_t maskB = (uint32_t)(rowlB & 7) << 4;
    const uint32_t bRowBase = (uint32_t)(wc * 64 + rowlB) * 128;

    const float fi0 = g_fs[row0 + wr * 16 + qg];
    const float fi1 = g_fs[row0 + wr * 16 + qg + 8];

    float acc[8][4];
    #pragma unroll
    for (int n = 0; n < 8; n++)
        #pragma unroll
        for (int c = 0; c < 4; c++) acc[n][c] = 0.f;

    float sld[2][LANEL]; int sli[2][LANEL];
    #pragma unroll
    for (int s = 0; s < 2; s++)
        #pragma unroll
        for (int k = 0; k < LANEL; k++) { sld[s][k] = 3.0e38f; sli[s][k] = 0; }

    mbar_wait_acq(MB_A, 0);    // A resident

    for (int st = 0; st < TOTST; st++) {
        const int kp = st & 3;           // chunk pair in tile
        const int tile = st >> 2;

        __syncthreads();   // all warps done with stage st-1 -> slot (st+2)%3 reusable
        if (tid == 0) {
            int sl = st + 2;
            if (sl < TOTST) {
                int slot = sl % NSTAGE;
                mbar_expect(MB_B + 8 * slot, 32768);
                bulk_g2s(sb + SM_B + (uint32_t)slot * 32768,
                         (const char*)g_featsb + ((size_t)(sl >> 2) * NCHUNK + (size_t)(sl & 3) * 2) * 16384,
                         32768, MB_B + 8 * slot);
            }
        }
        if (kp == 0 && tid < 128) sfs[tid] = g_fs[tile * 128 + tid];

        mbar_wait_acq(MB_B + 8 * (st % NSTAGE), (uint32_t)((st / NSTAGE) & 1));

        const uint32_t bstage = sb + SM_B + (uint32_t)(st % NSTAGE) * 32768 + bRowBase;

        #pragma unroll
        for (int cc = 0; cc < 2; cc++) {         // two chunks per stage
            const int kc = kp * 2 + cc;
            const uint32_t abase = sb + SM_A + (uint32_t)kc * 16384 + aRowBase;
            const uint32_t bbase = bstage + (uint32_t)cc * 16384;
            #pragma unroll
            for (int ks = 0; ks < 4; ks++) {
                uint32_t acol = ((uint32_t)(ks * 32 + halfA * 16)) ^ maskA;
                uint32_t bcol = ((uint32_t)(ks * 32 + halfB * 16)) ^ maskB;
                uint32_t a0, a1, a2, a3;
                ldsm4(a0, a1, a2, a3, abase + acol);
                #pragma unroll
                for (int p = 0; p < 4; p++) {
                    uint32_t b0, b1, b2, b3;
                    ldsm4(b0, b1, b2, b3, bbase + (uint32_t)p * 2048 + bcol);
                    mma16816(acc[2 * p],     a0, a1, a2, a3, b0, b1);
                    mma16816(acc[2 * p + 1], a0, a1, a2, a3, b2, b3);
                }
            }
        }

        if (kp == 3) {
            #pragma unroll
            for (int n8 = 0; n8 < 8; n8++) {
                int c0 = wc * 64 + n8 * 8 + 2 * t4;
                float fj0 = sfs[c0], fj1 = sfs[c0 + 1];
                int j = tile * 128 + c0;
                float v00 = fmaxf(fmaf(-2.f, acc[n8][0], fi0 + fj0), 1e-12f);
                float v01 = fmaxf(fmaf(-2.f, acc[n8][1], fi0 + fj1), 1e-12f);
                float v10 = fmaxf(fmaf(-2.f, acc[n8][2], fi1 + fj0), 1e-12f);
                float v11 = fmaxf(fmaf(-2.f, acc[n8][3], fi1 + fj1), 1e-12f);
                insL<LANEL>(sld[0], sli[0], v00, j);
                insL<LANEL>(sld[0], sli[0], v01, j + 1);
                insL<LANEL>(sld[1], sli[1], v10, j);
                insL<LANEL>(sld[1], sli[1], v11, j + 1);
                acc[n8][0] = 0.f; acc[n8][1] = 0.f;
                acc[n8][2] = 0.f; acc[n8][3] = 0.f;
            }
        }
    }

    // ---- final merge: 8 lane-lists x 9 per row -> top-16 (reuse A region) ----
    __syncthreads();
    float* dm = (float*)(smem + SM_A);                      // 128*72*4 = 36864
    int*   im = (int*)(smem + SM_A + 128 * 72 * 4);         // +36864
    {
        const int listid = wc * 4 + t4;                     // 8 lists per row
        #pragma unroll
        for (int h = 0; h < 2; h++) {
            int rloc = wr * 16 + h * 8 + qg;
            #pragma unroll
            for (int k = 0; k < LANEL; k++) {
                dm[rloc * 72 + listid * LANEL + k] = sld[h][k];
                im[rloc * 72 + listid * LANEL + k] = sli[h][k];
            }
        }
    }
    __syncthreads();
    if (tid < 128) {
        int row = row0 + tid;
        if (row < NQ) {
            float bd[SHORTL]; int bi[SHORTL];
            #pragma unroll
            for (int k = 0; k < SHORTL; k++) { bd[k] = 3.0e38f; bi[k] = 0; }
            for (int e = 0; e < 72; e++)
                insL<SHORTL>(bd, bi, dm[tid * 72 + e], im[tid * 72 + e]);
            #pragma unroll
            for (int k = 0; k < SHORTL; k++) g_short[(size_t)row * SHORTL + k] = bi[k];
        }
    }
}

// ---------------- kernel 4: exact fp32 re-rank + entropy + proto rank + scatter ----
__global__ __launch_bounds__(256) void rerank_kernel(const float* __restrict__ protos,
                                                     const int* __restrict__ sidx,
                                                     float* __restrict__ out) {
    const int q = blockIdx.x * 8 + (threadIdx.x >> 5);
    if (q >= NQ) return;
    const int lane = threadIdx.x & 31;
    const unsigned FULL = 0xffffffffu;

    float qv[16];
    const float* fr = g_feats + (size_t)q * CDIM;
    #pragma unroll
    for (int i = 0; i < 16; i++) qv[i] = fr[i * 32 + lane];
    const float fq = g_fs[q];

    int myidx = (lane < SHORTL) ? g_short[(size_t)q * SHORTL + lane] : 0x7fffffff;
    float myd = 1e38f;

    #pragma unroll 1
    for (int c = 0; c < SHORTL; c++) {
        int cj = __shfl_sync(FULL, myidx, c);
        const float* cr = g_feats + (size_t)cj * CDIM;
        float acc = 0.f;
        #pragma unroll
        for (int i = 0; i < 16; i++) acc += qv[i] * __ldg(&cr[i * 32 + lane]);
        #pragma unroll
        for (int o = 16; o > 0; o >>= 1) acc += __shfl_xor_sync(FULL, acc, o);
        float d = fmaxf(fq + __ldg(&g_fs[cj]) - 2.f * acc, 1e-12f);
        if (lane == c) myd = d;
    }

    int rank = 0;
    #pragma unroll
    for (int o = 0; o < SHORTL; o++) {
        float od = __shfl_sync(FULL, myd, o);
        int   oi = __shfl_sync(FULL, myidx, o);
        if (o != lane && (od < myd || (od == myd && oi < myidx))) rank++;
    }
    int nbcls = (lane < SHORTL && rank < KNN) ? g_cls[myidx] : -1;

    float ent = 0.f;
    #pragma unroll
    for (int c = 0; c < NCLS; c++) {
        int cnt = __popc(__ballot_sync(FULL, nbcls == c));
        if (cnt > 0) {
            float p = (float)cnt * (1.f / 9.f);
            ent += -p * logf(p + 1e-6f);
        }
    }
    ent *= (1.f / logf(19.f));

    float pd = 1e38f;
    #pragma unroll 1
    for (int c = 0; c < NCLS; c++) {
        float acc = 0.f;
        #pragma unroll
        for (int i = 0; i < 16; i++) acc += qv[i] * __ldg(&protos[c * CDIM + i * 32 + lane]);
        #pragma unroll
        for (int o = 16; o > 0; o >>= 1) acc += __shfl_xor_sync(FULL, acc, o);
        if (lane == c) pd = fmaxf(fq + g_psq[c] - 2.f * acc, 1e-12f);
    }
    int myc = g_cls[q];
    float refd = __shfl_sync(FULL, pd, myc);
    unsigned m = __ballot_sync(FULL, (lane < NCLS) && (pd < refd || (pd == refd && lane < myc)));
    int prank = __popc(m);

    if (lane == 0) {
        int s = sidx[q];
        out[s] = ent;
        out[FULLHW + s] = (float)prank * (1.f / 18.f);
    }
}

// ---------------- launch ----------------
extern "C" void kernel_launch(void* const* d_in, const int* in_sizes, int n_in,
                              void* d_out, int out_size) {
    const float* feat   = nullptr;
    const float* outp   = nullptr;
    const float* protos = nullptr;
    const int*   sidx   = nullptr;
    for (int i = 0; i < n_in; i++) {
        switch (in_sizes[i]) {
            case 66355200: feat   = (const float*)d_in[i]; break;
            case 2462400:  outp   = (const float*)d_in[i]; break;
            case 9728:     protos = (const float*)d_in[i]; break;
            case 32400:    sidx   = (const int*)d_in[i];   break;
        }
    }
    float* out = (float*)d_out;

    static bool attr_done = false;
    if (!attr_done) {
        cudaFuncSetAttribute(dist_select_kernel,
                             cudaFuncAttributeMaxDynamicSharedMemorySize, SM_TOTAL);
        attr_done = true;
    }

    int n4 = out_size / 4;
    zpsq_kernel<<<(n4 + 255) / 256, 256>>>(protos, (float4*)out, n4);
    prep_kernel<<<NQ, 128>>>(feat, outp, sidx);
    convert_kernel<<<(NT * 64 + 255) / 256, 256>>>();
    dist_select_kernel<<<ROWBLKS, 512, SM_TOTAL>>>();
    rerank_kernel<<<(NQ + 7) / 8, 256>>>(protos, sidx, out);
}

// round 8
// speedup vs baseline: 6.5095x; 1.1014x over previous
#include <cuda_runtime.h>
#include <cuda_bf16.h>
#include <math.h>
#include <cstdint>

#define NQ 32400
#define NT 32512          // 254*128 padded
#define CDIM 512
#define NCLS 19
#define KNN 9
#define SHORTL 16
#define LANEL 9
#define HWIN (270*480)
#define FULLHW (1080*1920)
#define NCHUNK 8          // K chunks of 64 bf16 (128B rows)
#define NTILE 254         // candidate tiles of 128
#define TOT (NTILE*NCHUNK)
#define QBLKS 127         // 256-row query blocks
#define NSTAGE 3
#define STAGEB 49152      // 32KB A + 16KB B

// ---------------- device scratch ----------------
__device__ float g_feats[(size_t)NT * CDIM];   // fp32 gathered feats
__device__ float g_fs[NT];                     // |f|^2 (pads -> 1e30)
__device__ int   g_cls[NQ];
__device__ float g_psq[NCLS];
// bf16 feats, TILE-major: [tile][chunk][128 rows x 128B], SW128 pre-swizzled per 8-row atom
__device__ __align__(1024) __nv_bfloat16 g_featsb[(size_t)NCHUNK * NT * 64];
__device__ int g_short[(size_t)NT * SHORTL];

// ---------------- helpers ----------------
__device__ __forceinline__ uint32_t smem_u32(const void* p) {
    uint32_t a;
    asm("{ .reg .u64 t; cvta.to.shared.u64 t, %1; cvt.u32.u64 %0, t; }" : "=r"(a) : "l"(p));
    return a;
}
__device__ __forceinline__ void mbar_init(uint32_t a, uint32_t n) {
    asm volatile("mbarrier.init.shared.b64 [%0], %1;" :: "r"(a), "r"(n) : "memory");
}
__device__ __forceinline__ void mbar_expect(uint32_t a, uint32_t bytes) {
    asm volatile("mbarrier.arrive.expect_tx.shared.b64 _, [%0], %1;" :: "r"(a), "r"(bytes) : "memory");
}
__device__ __forceinline__ void mbar_wait_acq(uint32_t a, uint32_t ph) {
    asm volatile(
        "{\n\t.reg .pred P;\n"
        "W%=:\n\t"
        "mbarrier.try_wait.parity.acquire.cta.shared::cta.b64 P, [%0], %1, 0x989680;\n\t"
        "@P bra D%=;\n\t"
        "bra W%=;\n"
        "D%=:\n\t}"
        :: "r"(a), "r"(ph) : "memory");
}
__device__ __forceinline__ void bulk_g2s(uint32_t dst, const void* src, uint32_t bytes, uint32_t mbar) {
    asm volatile(
        "cp.async.bulk.shared::cluster.global.mbarrier::complete_tx::bytes [%0], [%1], %2, [%3];"
        :: "r"(dst), "l"(src), "r"(bytes), "r"(mbar) : "memory");
}
__device__ __forceinline__ void fence_async_shared() {
    asm volatile("fence.proxy.async.shared::cta;" ::: "memory");
}
__device__ __forceinline__ void ldsm4(uint32_t& r0, uint32_t& r1, uint32_t& r2, uint32_t& r3, uint32_t addr) {
    asm volatile("ldmatrix.sync.aligned.m8n8.x4.shared.b16 {%0,%1,%2,%3}, [%4];"
                 : "=r"(r0), "=r"(r1), "=r"(r2), "=r"(r3) : "r"(addr));
}
__device__ __forceinline__ void mma16816(float* c, uint32_t a0, uint32_t a1, uint32_t a2, uint32_t a3,
                                         uint32_t b0, uint32_t b1) {
    asm volatile("mma.sync.aligned.m16n8k16.row.col.f32.bf16.bf16.f32 "
                 "{%0,%1,%2,%3}, {%4,%5,%6,%7}, {%8,%9}, {%0,%1,%2,%3};"
                 : "+f"(c[0]), "+f"(c[1]), "+f"(c[2]), "+f"(c[3])
                 : "r"(a0), "r"(a1), "r"(a2), "r"(a3), "r"(b0), "r"(b1));
}
__device__ __forceinline__ uint32_t sw128(uint32_t x) { return x ^ ((x >> 3) & 0x70); }

template<int L>
__device__ __forceinline__ void insL(float (&d)[L], int (&ix)[L], float v, int j) {
    if (v < d[L - 1]) {
        d[L - 1] = v; ix[L - 1] = j;
        #pragma unroll
        for (int p = L - 1; p > 0; p--) {
            if (d[p] < d[p - 1]) {
                float tf = d[p]; d[p] = d[p - 1]; d[p - 1] = tf;
                int   ti = ix[p]; ix[p] = ix[p - 1]; ix[p - 1] = ti;
            }
        }
    }
}

// ---------------- kernel 0: zero output + prototype norms + fs pad ----------------
__global__ void zpsq_kernel(const float* __restrict__ protos, float4* out, int n4) {
    int i = blockIdx.x * blockDim.x + threadIdx.x;
    if (i < n4) out[i] = make_float4(0.f, 0.f, 0.f, 0.f);
    if (blockIdx.x == 0) {
        int tid = threadIdx.x;
        int w = tid >> 5, lane = tid & 31;
        for (int c = w; c < NCLS; c += 8) {
            float sacc = 0.f;
            for (int k = lane; k < CDIM; k += 32) {
                float v = protos[c * CDIM + k];
                sacc += v * v;
            }
            #pragma unroll
            for (int o = 16; o > 0; o >>= 1) sacc += __shfl_xor_sync(0xffffffffu, sacc, o);
            if (lane == 0) g_psq[c] = sacc;
        }
        if (tid < NT - NQ) g_fs[NQ + tid] = 1e30f;
    }
}

// ---------------- kernel 1: gather feats, |f|^2, argmax class ----------------
__global__ void prep_kernel(const float* __restrict__ feat,
                            const float* __restrict__ outp,
                            const int* __restrict__ sidx) {
    const int i = blockIdx.x;
    const int tid = threadIdx.x;
    const int s = sidx[i];

    float acc = 0.f;
    float* dst = g_feats + (size_t)i * CDIM;
    for (int c = tid; c < CDIM; c += 128) {
        float v = __ldg(feat + (size_t)c * HWIN + s);
        dst[c] = v;
        acc += v * v;
    }
    __shared__ float red[128];
    __shared__ float sval[NCLS];
    red[tid] = acc;
    if (tid < NCLS) sval[tid] = __ldg(outp + (size_t)tid * HWIN + s);
    __syncthreads();
    for (int st = 64; st > 0; st >>= 1) {
        if (tid < st) red[tid] += red[tid + st];
        __syncthreads();
    }
    if (tid == 0) {
        g_fs[i] = red[0];
        float best = sval[0]; int bc = 0;
        #pragma unroll
        for (int c = 1; c < NCLS; c++)
            if (sval[c] > best) { best = sval[c]; bc = c; }
        g_cls[i] = bc;
    }
}

// ---------------- kernel 2: fp32 -> bf16, tile-major, pre-swizzled (pads zeroed) ----
__global__ void convert_kernel() {
    int idx = blockIdx.x * blockDim.x + threadIdx.x;   // one 16B group of 8 bf16
    if (idx >= NT * 64) return;
    int r  = idx >> 6;
    int g8 = idx & 63;
    int k  = g8 * 8;
    int c  = k >> 6;
    int kin = k & 63;

    uint4 u = make_uint4(0u, 0u, 0u, 0u);
    if (r < NQ) {
        const float4* src = (const float4*)(g_feats + (size_t)r * CDIM + k);
        float4 v0 = src[0], v1 = src[1];
        __nv_bfloat162 p0 = __floats2bfloat162_rn(v0.x, v0.y);
        __nv_bfloat162 p1 = __floats2bfloat162_rn(v0.z, v0.w);
        __nv_bfloat162 p2 = __floats2bfloat162_rn(v1.x, v1.y);
        __nv_bfloat162 p3 = __floats2bfloat162_rn(v1.z, v1.w);
        u.x = *(uint32_t*)&p0; u.y = *(uint32_t*)&p1;
        u.z = *(uint32_t*)&p2; u.w = *(uint32_t*)&p3;
    }
    // tile-major: [tile][chunk][16 atoms x 1024B]
    size_t base = ((size_t)(r >> 7) * NCHUNK + c) * 16384 + (size_t)((r >> 3) & 15) * 1024;
    uint32_t inner = (uint32_t)((r & 7) * 128 + kin * 2);
    *(uint4*)((char*)g_featsb + base + sw128(inner)) = u;
}

// ---------------- kernel 3: HMMA GEMM + fused top-K (M=256, streamed A, transpose epi) ----
#define SM_FS 0
#define SM_STG 1024
#define SM_TOTAL (SM_STG + NSTAGE * STAGEB)   // 148480

__global__ __launch_bounds__(512, 1) void dist_select_kernel() {
    extern __shared__ char smem[];
    const uint32_t sb = smem_u32(smem);
    float* sfs = (float*)(smem + SM_FS);
    const uint32_t MB = sb + 512;          // 3 x 8B

    const int tid = threadIdx.x;
    const int w = tid >> 5, l = tid & 31;
    const int qg = l >> 2, t4 = l & 3;
    const int wr = w >> 1, wc = w & 1;     // 8x2 warp grid: 32 rows x 64 cols per warp
    const int blk = blockIdx.x;
    const int row0 = blk * 256;
    const unsigned FULL = 0xffffffffu;

    if (tid == 0) {
        #pragma unroll
        for (int s = 0; s < NSTAGE; s++) mbar_init(MB + 8 * s, 1);
        fence_async_shared();
    }
    __syncthreads();

    // prologue: stages for it=0,1 (A chunk + B chunk each)
    if (tid == 0) {
        #pragma unroll
        for (int it0 = 0; it0 < 2; it0++) {
            uint32_t dst = sb + SM_STG + (uint32_t)it0 * STAGEB;
            mbar_expect(MB + 8 * it0, STAGEB);
            bulk_g2s(dst,         (const char*)g_featsb + ((size_t)(2 * blk)     * NCHUNK + it0) * 16384, 16384, MB + 8 * it0);
            bulk_g2s(dst + 16384, (const char*)g_featsb + ((size_t)(2 * blk + 1) * NCHUNK + it0) * 16384, 16384, MB + 8 * it0);
            bulk_g2s(dst + 32768, (const char*)g_featsb + (size_t)it0 * 16384, 16384, MB + 8 * it0);
        }
    }

    // ---- per-lane ldmatrix addressing ----
    const int rowlA = l & 15;
    const int halfA = (l >> 4) & 1;
    const uint32_t maskA = (uint32_t)(rowlA & 7) << 4;
    const uint32_t aRowBase = (uint32_t)(wr * 32 + rowlA) * 128;
    const int rowlB = (l & 7) + ((l >> 4) << 3);
    const int halfB = (l >> 3) & 1;
    const uint32_t maskB = (uint32_t)(rowlB & 7) << 4;
    const uint32_t bRowBase = 32768 + (uint32_t)(wc * 64 + rowlB) * 128;

    // after transpose, this lane owns query row:
    const int rown = wr * 32 + qg + 8 * t4;
    const float fi = g_fs[row0 + rown];

    float acc[2][8][4];
    #pragma unroll
    for (int m = 0; m < 2; m++)
        #pragma unroll
        for (int n = 0; n < 8; n++)
            #pragma unroll
            for (int c = 0; c < 4; c++) acc[m][n][c] = 0.f;

    float ld9[LANEL]; int li9[LANEL];
    #pragma unroll
    for (int k = 0; k < LANEL; k++) { ld9[k] = 3.0e38f; li9[k] = 0; }

    for (int it = 0; it < TOT; it++) {
        const int kc = it & 7;
        const int tile = it >> 3;

        __syncthreads();   // all warps done with stage it-1 -> slot (it+2)%3 reusable
        if (tid == 0) {
            int il = it + 2;
            if (il < TOT) {
                int slot = il % NSTAGE;
                int t2 = il >> 3, k2 = il & 7;
                uint32_t dst = sb + SM_STG + (uint32_t)slot * STAGEB;
                mbar_expect(MB + 8 * slot, STAGEB);
                bulk_g2s(dst,         (const char*)g_featsb + ((size_t)(2 * blk)     * NCHUNK + k2) * 16384, 16384, MB + 8 * slot);
                bulk_g2s(dst + 16384, (const char*)g_featsb + ((size_t)(2 * blk + 1) * NCHUNK + k2) * 16384, 16384, MB + 8 * slot);
                bulk_g2s(dst + 32768, (const char*)g_featsb + ((size_t)t2 * NCHUNK + k2) * 16384, 16384, MB + 8 * slot);
            }
        }
        if (kc == 0 && tid < 128) sfs[tid] = g_fs[tile * 128 + tid];

        mbar_wait_acq(MB + 8 * (it % NSTAGE), (uint32_t)((it / NSTAGE) & 1));

        const uint32_t stg = sb + SM_STG + (uint32_t)(it % NSTAGE) * STAGEB;
        const uint32_t abase = stg + aRowBase;
        const uint32_t bbase = stg + bRowBase;

        #pragma unroll
        for (int ks = 0; ks < 4; ks++) {
            uint32_t acol = ((uint32_t)(ks * 32 + halfA * 16)) ^ maskA;
            uint32_t bcol = ((uint32_t)(ks * 32 + halfB * 16)) ^ maskB;
            uint32_t a00, a01, a02, a03, a10, a11, a12, a13;
            ldsm4(a00, a01, a02, a03, abase + acol);
            ldsm4(a10, a11, a12, a13, abase + 2048 + acol);
            #pragma unroll
            for (int p = 0; p < 4; p++) {
                uint32_t b0, b1, b2, b3;
                ldsm4(b0, b1, b2, b3, bbase + (uint32_t)p * 2048 + bcol);
                mma16816(acc[0][2 * p],     a00, a01, a02, a03, b0, b1);
                mma16816(acc[0][2 * p + 1], a00, a01, a02, a03, b2, b3);
                mma16816(acc[1][2 * p],     a10, a11, a12, a13, b0, b1);
                mma16816(acc[1][2 * p + 1], a10, a11, a12, a13, b2, b3);
            }
        }

        if (kc == 7) {
            // quad transpose: lane t4 gets full row (its 64 warp cols), then select
            const int jb = tile * 128 + wc * 64;
            #pragma unroll
            for (int n8 = 0; n8 < 8; n8++) {
                #pragma unroll
                for (int cb = 0; cb < 2; cb++) {
                    float e0 = acc[0][n8][cb],     e1 = acc[0][n8][2 + cb];
                    float e2 = acc[1][n8][cb],     e3 = acc[1][n8][2 + cb];
                    // round 1 (xor lane bit0 <-> slot bit0)
                    float s0 = __shfl_xor_sync(FULL, e1, 1);
                    float s1 = __shfl_xor_sync(FULL, e0, 1);
                    float s2 = __shfl_xor_sync(FULL, e3, 1);
                    float s3 = __shfl_xor_sync(FULL, e2, 1);
                    bool lo = ((t4 & 1) == 0);
                    float y0 = lo ? e0 : s0;
                    float y1 = lo ? s1 : e1;
                    float y2 = lo ? e2 : s2;
                    float y3 = lo ? s3 : e3;
                    // round 2 (xor lane bit1 <-> slot bit1)
                    float u0 = __shfl_xor_sync(FULL, y2, 2);
                    float u1 = __shfl_xor_sync(FULL, y3, 2);
                    float u2 = __shfl_xor_sync(FULL, y0, 2);
                    float u3 = __shfl_xor_sync(FULL, y1, 2);
                    bool hi = ((t4 & 2) == 0);
                    float x0 = hi ? y0 : u0;
                    float x1 = hi ? y1 : u1;
                    float x2 = hi ? u2 : y2;
                    float x3 = hi ? u3 : y3;
                    // x[s] = dot for col n8*8 + 2*s + cb of this lane's row
                    int c0 = n8 * 8 + cb;
                    float d0 = fmaxf(fmaf(-2.f, x0, fi + sfs[wc * 64 + c0]),     1e-12f);
                    float d1 = fmaxf(fmaf(-2.f, x1, fi + sfs[wc * 64 + c0 + 2]), 1e-12f);
                    float d2 = fmaxf(fmaf(-2.f, x2, fi + sfs[wc * 64 + c0 + 4]), 1e-12f);
                    float d3 = fmaxf(fmaf(-2.f, x3, fi + sfs[wc * 64 + c0 + 6]), 1e-12f);
                    insL<LANEL>(ld9, li9, d0, jb + c0);
                    insL<LANEL>(ld9, li9, d1, jb + c0 + 2);
                    insL<LANEL>(ld9, li9, d2, jb + c0 + 4);
                    insL<LANEL>(ld9, li9, d3, jb + c0 + 6);
                }
            }
            #pragma unroll
            for (int m = 0; m < 2; m++)
                #pragma unroll
                for (int n = 0; n < 8; n++)
                    #pragma unroll
                    for (int c = 0; c < 4; c++) acc[m][n][c] = 0.f;
        }
    }

    // ---- final merge: 2 half-lists x 9 per row -> top-16 ----
    __syncthreads();
    float* dm = (float*)(smem + SM_STG);                       // 256*18*4 = 18432
    int*   im = (int*)(smem + SM_STG + 256 * 18 * 4);          // +18432
    #pragma unroll
    for (int k = 0; k < LANEL; k++) {
        dm[rown * 18 + wc * LANEL + k] = ld9[k];
        im[rown * 18 + wc * LANEL + k] = li9[k];
    }
    __syncthreads();
    if (tid < 256) {
        int row = row0 + tid;
        if (row < NQ) {
            float bd[SHORTL]; int bi[SHORTL];
            #pragma unroll
            for (int k = 0; k < SHORTL; k++) { bd[k] = 3.0e38f; bi[k] = 0; }
            #pragma unroll
            for (int e = 0; e < 18; e++)
                insL<SHORTL>(bd, bi, dm[tid * 18 + e], im[tid * 18 + e]);
            #pragma unroll
            for (int k = 0; k < SHORTL; k++) g_short[(size_t)row * SHORTL + k] = bi[k];
        }
    }
}

// ---------------- kernel 4: exact fp32 re-rank + entropy + proto rank + scatter ----
__global__ __launch_bounds__(256) void rerank_kernel(const float* __restrict__ protos,
                                                     const int* __restrict__ sidx,
                                                     float* __restrict__ out) {
    const int q = blockIdx.x * 8 + (threadIdx.x >> 5);
    if (q >= NQ) return;
    const int lane = threadIdx.x & 31;
    const unsigned FULL = 0xffffffffu;

    float qv[16];
    const float* fr = g_feats + (size_t)q * CDIM;
    #pragma unroll
    for (int i = 0; i < 16; i++) qv[i] = fr[i * 32 + lane];
    const float fq = g_fs[q];

    int myidx = (lane < SHORTL) ? g_short[(size_t)q * SHORTL + lane] : 0x7fffffff;
    float myd = 1e38f;

    #pragma unroll 1
    for (int c = 0; c < SHORTL; c++) {
        int cj = __shfl_sync(FULL, myidx, c);
        const float* cr = g_feats + (size_t)cj * CDIM;
        float acc = 0.f;
        #pragma unroll
        for (int i = 0; i < 16; i++) acc += qv[i] * __ldg(&cr[i * 32 + lane]);
        #pragma unroll
        for (int o = 16; o > 0; o >>= 1) acc += __shfl_xor_sync(FULL, acc, o);
        float d = fmaxf(fq + __ldg(&g_fs[cj]) - 2.f * acc, 1e-12f);
        if (lane == c) myd = d;
    }

    int rank = 0;
    #pragma unroll
    for (int o = 0; o < SHORTL; o++) {
        float od = __shfl_sync(FULL, myd, o);
        int   oi = __shfl_sync(FULL, myidx, o);
        if (o != lane && (od < myd || (od == myd && oi < myidx))) rank++;
    }
    int nbcls = (lane < SHORTL && rank < KNN) ? g_cls[myidx] : -1;

    float ent = 0.f;
    #pragma unroll
    for (int c = 0; c < NCLS; c++) {
        int cnt = __popc(__ballot_sync(FULL, nbcls == c));
        if (cnt > 0) {
            float p = (float)cnt * (1.f / 9.f);
            ent += -p * logf(p + 1e-6f);
        }
    }
    ent *= (1.f / logf(19.f));

    float pd = 1e38f;
    #pragma unroll 1
    for (int c = 0; c < NCLS; c++) {
        float acc = 0.f;
        #pragma unroll
        for (int i = 0; i < 16; i++) acc += qv[i] * __ldg(&protos[c * CDIM + i * 32 + lane]);
        #pragma unroll
        for (int o = 16; o > 0; o >>= 1) acc += __shfl_xor_sync(FULL, acc, o);
        if (lane == c) pd = fmaxf(fq + g_psq[c] - 2.f * acc, 1e-12f);
    }
    int myc = g_cls[q];
    float refd = __shfl_sync(FULL, pd, myc);
    unsigned m = __ballot_sync(FULL, (lane < NCLS) && (pd < refd || (pd == refd && lane < myc)));
    int prank = __popc(m);

    if (lane == 0) {
        int s = sidx[q];
        out[s] = ent;
        out[FULLHW + s] = (float)prank * (1.f / 18.f);
    }
}

// ---------------- launch ----------------
extern "C" void kernel_launch(void* const* d_in, const int* in_sizes, int n_in,
                              void* d_out, int out_size) {
    const float* feat   = nullptr;
    const float* outp   = nullptr;
    const float* protos = nullptr;
    const int*   sidx   = nullptr;
    for (int i = 0; i < n_in; i++) {
        switch (in_sizes[i]) {
            case 66355200: feat   = (const float*)d_in[i]; break;
            case 2462400:  outp   = (const float*)d_in[i]; break;
            case 9728:     protos = (const float*)d_in[i]; break;
            case 32400:    sidx   = (const int*)d_in[i];   break;
        }
    }
    float* out = (float*)d_out;

    static bool attr_done = false;
    if (!attr_done) {
        cudaFuncSetAttribute(dist_select_kernel,
                             cudaFuncAttributeMaxDynamicSharedMemorySize, SM_TOTAL);
        attr_done = true;
    }

    int n4 = out_size / 4;
    zpsq_kernel<<<(n4 + 255) / 256, 256>>>(protos, (float4*)out, n4);
    prep_kernel<<<NQ, 128>>>(feat, outp, sidx);
    convert_kernel<<<(NT * 64 + 255) / 256, 256>>>();
    dist_select_kernel<<<QBLKS, 512, SM_TOTAL>>>();
    rerank_kernel<<<(NQ + 7) / 8, 256>>>(protos, sidx, out);
}